// round 2
// baseline (speedup 1.0000x reference)
#include <cuda_runtime.h>
#include <cuda_bf16.h>
#include <math.h>

// Problem constants (fixed by setup_inputs)
#define NNODES 100000
#define F0 512
#define F1 256
#define F2 40
#define EDGES 3200000

// ---------------- scratch (device globals; no allocations allowed) ----------
__device__ float g_dis[NNODES];            // deg_inv_sqrt
__device__ int   g_cnt[NNODES];            // in-degree (excl. self loop)
__device__ int   g_off[NNODES + 1];        // CSR offsets by dst
__device__ int   g_pos[NNODES];            // fill cursors
__device__ int   g_srcs[EDGES];            // CSR column (src) array
__device__ float g_h1 [(size_t)NNODES * F1];   // x @ W1
__device__ float g_h1a[(size_t)NNODES * F1];   // relu(agg(h1) + b1)
__device__ float g_h2 [(size_t)NNODES * F2];   // h1a @ W2

// ---------------- CSR build --------------------------------------------------
__global__ void k_zero_cnt() {
    int i = blockIdx.x * blockDim.x + threadIdx.x;
    if (i < NNODES) g_cnt[i] = 0;
}

__global__ void k_count(const int* __restrict__ dst) {
    int e = blockIdx.x * blockDim.x + threadIdx.x;
    if (e < EDGES) {
        int d = dst[e];
        if ((unsigned)d < (unsigned)NNODES) atomicAdd(&g_cnt[d], 1);
    }
}

// Single-block exclusive scan over 100000 counters; also computes
// deg_inv_sqrt (deg = cnt + 1 for the self loop) and inits fill cursors.
__global__ void k_scan() {
    __shared__ int part[1024];
    const int t  = threadIdx.x;
    const int CH = (NNODES + 1023) / 1024;          // 98
    int lo = t * CH;
    int hi = lo + CH; if (hi > NNODES) hi = NNODES;
    int s = 0;
    for (int i = lo; i < hi; i++) s += g_cnt[i];
    part[t] = s;
    __syncthreads();
    // inclusive Hillis-Steele scan of per-thread partials
    for (int d = 1; d < 1024; d <<= 1) {
        int add = (t >= d) ? part[t - d] : 0;
        __syncthreads();
        part[t] += add;
        __syncthreads();
    }
    int run = part[t] - s;                           // exclusive prefix
    for (int i = lo; i < hi; i++) {
        int c = g_cnt[i];
        g_off[i] = run;
        g_pos[i] = run;
        g_dis[i] = rsqrtf((float)(c + 1));
        run += c;
    }
    if (t == 1023) g_off[NNODES] = run;              // == EDGES
}

__global__ void k_fill(const int* __restrict__ src,
                       const int* __restrict__ dst) {
    int e = blockIdx.x * blockDim.x + threadIdx.x;
    if (e < EDGES) {
        int d = dst[e];
        int s = src[e];
        if ((unsigned)d < (unsigned)NNODES && (unsigned)s < (unsigned)NNODES) {
            int p = atomicAdd(&g_pos[d], 1);
            g_srcs[p] = s;
        }
    }
}

// ---------------- GEMM1: g_h1 = x[100000x512] @ W1[512x256] ------------------
// Classic 128x128x8 tiled SGEMM, 256 threads, 8x8 outputs/thread.
__global__ __launch_bounds__(256, 2)
void k_sgemm1(const float* __restrict__ A, const float* __restrict__ B) {
    const int M = NNODES, K = F0, NC = F1;
    __shared__ float As[8][128];
    __shared__ float Bs[8][128];
    const int tid = threadIdx.x;
    const int blockRow = blockIdx.y * 128;
    const int blockCol = blockIdx.x * 128;

    const int aRow = tid >> 1;           // 0..127
    const int aK4  = (tid & 1) * 4;      // 0 or 4
    const int bK   = tid >> 5;           // 0..7
    const int bCol = (tid & 31) * 4;     // 0..124
    const int tRow = (tid >> 4) * 8;
    const int tCol = (tid & 15) * 8;

    float acc[8][8];
#pragma unroll
    for (int i = 0; i < 8; i++)
#pragma unroll
        for (int j = 0; j < 8; j++) acc[i][j] = 0.f;

    for (int k0 = 0; k0 < K; k0 += 8) {
        float4 av;
        int gRow = blockRow + aRow;
        if (gRow < M) av = *(const float4*)(A + (size_t)gRow * K + k0 + aK4);
        else          av = make_float4(0.f, 0.f, 0.f, 0.f);
        As[aK4 + 0][aRow] = av.x;
        As[aK4 + 1][aRow] = av.y;
        As[aK4 + 2][aRow] = av.z;
        As[aK4 + 3][aRow] = av.w;
        float4 bv = *(const float4*)(B + (size_t)(k0 + bK) * NC + blockCol + bCol);
        *(float4*)&Bs[bK][bCol] = bv;
        __syncthreads();
#pragma unroll
        for (int kk = 0; kk < 8; kk++) {
            float a[8], b[8];
            *(float4*)&a[0] = *(float4*)&As[kk][tRow];
            *(float4*)&a[4] = *(float4*)&As[kk][tRow + 4];
            *(float4*)&b[0] = *(float4*)&Bs[kk][tCol];
            *(float4*)&b[4] = *(float4*)&Bs[kk][tCol + 4];
#pragma unroll
            for (int i = 0; i < 8; i++)
#pragma unroll
                for (int j = 0; j < 8; j++) acc[i][j] += a[i] * b[j];
        }
        __syncthreads();
    }
#pragma unroll
    for (int i = 0; i < 8; i++) {
        int gRow = blockRow + tRow + i;
        if (gRow < M) {
            float* out = g_h1 + (size_t)gRow * NC + blockCol + tCol;
            *(float4*)(out)     = make_float4(acc[i][0], acc[i][1], acc[i][2], acc[i][3]);
            *(float4*)(out + 4) = make_float4(acc[i][4], acc[i][5], acc[i][6], acc[i][7]);
        }
    }
}

// ---------------- agg1: h1a = relu( Â h1 + b1 ) ------------------------------
// One 64-thread block per node; thread t owns features [4t, 4t+4).
__global__ __launch_bounds__(64)
void k_agg1(const float* __restrict__ b1) {
    const int node = blockIdx.x;
    const int t = threadIdx.x;
    const float di = g_dis[node];
    const size_t col = (size_t)t * 4;

    float4 acc = *(const float4*)(g_h1 + (size_t)node * F1 + col);
    const float w0 = di * di;               // self-loop norm
    acc.x *= w0; acc.y *= w0; acc.z *= w0; acc.w *= w0;

    const int beg = g_off[node], end = g_off[node + 1];
    for (int e = beg; e < end; e++) {
        int s = g_srcs[e];
        float w = di * g_dis[s];
        float4 v = *(const float4*)(g_h1 + (size_t)s * F1 + col);
        acc.x += v.x * w; acc.y += v.y * w;
        acc.z += v.z * w; acc.w += v.w * w;
    }
    float4 bb = *(const float4*)(b1 + col);
    acc.x = fmaxf(acc.x + bb.x, 0.f);
    acc.y = fmaxf(acc.y + bb.y, 0.f);
    acc.z = fmaxf(acc.z + bb.z, 0.f);
    acc.w = fmaxf(acc.w + bb.w, 0.f);
    *(float4*)(g_h1a + (size_t)node * F1 + col) = acc;
}

// ---------------- GEMM2: g_h2 = h1a[100000x256] @ W2[256x40] -----------------
// W2 in smem (padded stride 41 -> conflict-free), one warp per row.
__global__ __launch_bounds__(256)
void k_gemm2(const float* __restrict__ W2) {
    __shared__ float Ws[F1 * 41];
    const int tid = threadIdx.x;
    for (int i = tid; i < F1 * F2; i += 256) {
        int k = i / F2, j = i % F2;
        Ws[k * 41 + j] = W2[i];
    }
    __syncthreads();
    const int warp = tid >> 5, lane = tid & 31;
    const int row = blockIdx.x * 8 + warp;
    if (row >= NNODES) return;

    float acc[F2];
#pragma unroll
    for (int j = 0; j < F2; j++) acc[j] = 0.f;

    for (int k = lane; k < F1; k += 32) {
        float a = g_h1a[(size_t)row * F1 + k];
        const float* w = &Ws[k * 41];
#pragma unroll
        for (int j = 0; j < F2; j++) acc[j] += a * w[j];
    }
#pragma unroll
    for (int j = 0; j < F2; j++) {
        float v = acc[j];
        v += __shfl_xor_sync(0xffffffffu, v, 16);
        v += __shfl_xor_sync(0xffffffffu, v, 8);
        v += __shfl_xor_sync(0xffffffffu, v, 4);
        v += __shfl_xor_sync(0xffffffffu, v, 2);
        v += __shfl_xor_sync(0xffffffffu, v, 1);
        acc[j] = v;
    }
    if (lane == 0) {
        float* out = g_h2 + (size_t)row * F2;
#pragma unroll
        for (int j = 0; j < F2; j++) out[j] = acc[j];
    }
}

// ---------------- agg2 + bias + log_softmax -> d_out -------------------------
// One warp per node. Lane owns feature `lane` (+ feature lane+32 if lane<8).
__global__ __launch_bounds__(128)
void k_agg2(const float* __restrict__ b2, float* __restrict__ out) {
    const int node = blockIdx.x * 4 + (threadIdx.x >> 5);
    const int lane = threadIdx.x & 31;
    if (node >= NNODES) return;
    const float di = g_dis[node];

    float a0, a1 = 0.f;
    {
        const float w0 = di * di;
        const float* h = g_h2 + (size_t)node * F2;
        a0 = h[lane] * w0;
        if (lane < 8) a1 = h[32 + lane] * w0;
    }
    const int beg = g_off[node], end = g_off[node + 1];
    for (int e = beg; e < end; e++) {
        int s = g_srcs[e];
        float w = di * g_dis[s];
        const float* h = g_h2 + (size_t)s * F2;
        a0 += h[lane] * w;
        if (lane < 8) a1 += h[32 + lane] * w;
    }
    a0 += b2[lane];
    a1 = (lane < 8) ? (a1 + b2[32 + lane]) : -3.4e38f;

    // warp-wide max
    float m = fmaxf(a0, a1);
    m = fmaxf(m, __shfl_xor_sync(0xffffffffu, m, 16));
    m = fmaxf(m, __shfl_xor_sync(0xffffffffu, m, 8));
    m = fmaxf(m, __shfl_xor_sync(0xffffffffu, m, 4));
    m = fmaxf(m, __shfl_xor_sync(0xffffffffu, m, 2));
    m = fmaxf(m, __shfl_xor_sync(0xffffffffu, m, 1));
    // warp-wide sum of exp
    float s0 = expf(a0 - m) + ((lane < 8) ? expf(a1 - m) : 0.f);
    s0 += __shfl_xor_sync(0xffffffffu, s0, 16);
    s0 += __shfl_xor_sync(0xffffffffu, s0, 8);
    s0 += __shfl_xor_sync(0xffffffffu, s0, 4);
    s0 += __shfl_xor_sync(0xffffffffu, s0, 2);
    s0 += __shfl_xor_sync(0xffffffffu, s0, 1);
    const float ls = logf(s0) + m;

    float* o = out + (size_t)node * F2;
    o[lane] = a0 - ls;
    if (lane < 8) o[32 + lane] = a1 - ls;
}

// ---------------- launch -----------------------------------------------------
extern "C" void kernel_launch(void* const* d_in, const int* in_sizes, int n_in,
                              void* d_out, int out_size) {
    const float* x   = (const float*)d_in[0];
    const float* W1  = (const float*)d_in[1];
    const float* b1  = (const float*)d_in[2];
    const float* W2  = (const float*)d_in[3];
    const float* b2  = (const float*)d_in[4];
    const int*   ei  = (const int*)d_in[5];   // JAX default: int64 demoted to int32
    const int*   src = ei;
    const int*   dst = ei + EDGES;
    float* out = (float*)d_out;

    k_zero_cnt<<<(NNODES + 255) / 256, 256>>>();
    k_count   <<<(EDGES + 255) / 256, 256>>>(dst);
    k_scan    <<<1, 1024>>>();
    k_fill    <<<(EDGES + 255) / 256, 256>>>(src, dst);

    dim3 g1(F1 / 128, (NNODES + 127) / 128);
    k_sgemm1<<<g1, 256>>>(x, W1);
    k_agg1  <<<NNODES, 64>>>(b1);
    k_gemm2 <<<(NNODES + 7) / 8, 256>>>(W2);
    k_agg2  <<<(NNODES + 3) / 4, 128>>>(b2, out);
}

// round 4
// speedup vs baseline: 1.2479x; 1.2479x over previous
#include <cuda_runtime.h>
#include <cuda_bf16.h>
#include <math.h>
#include <stdint.h>

// Problem constants (fixed by setup_inputs)
#define NNODES 100000
#define F0 512
#define F1 256
#define F2 40
#define EDGES 3200000

#define MPAD 100096            // 782 * 128

// ---------------- scratch (device globals; no allocations allowed) ----------
__device__ float g_dis[NNODES];            // deg_inv_sqrt
__device__ int   g_cnt[NNODES];            // in-degree (excl. self loop)
__device__ int   g_off[NNODES + 1];        // CSR offsets by dst
__device__ int   g_pos[NNODES];            // fill cursors
__device__ int   g_srcs[EDGES];            // CSR column (src) array
__device__ float g_h1 [(size_t)NNODES * F1];   // x @ W1
__device__ float g_h1a[(size_t)NNODES * F1];   // relu(agg(h1) + b1)
__device__ float g_h2 [(size_t)NNODES * F2];   // h1a @ W2

// bf16-split operands for HMMA GEMM1
__device__ uint16_t g_Axhi[(size_t)MPAD * F0];
__device__ uint16_t g_Axlo[(size_t)MPAD * F0];
__device__ uint16_t g_Bhi [(size_t)F1 * F0];     // [n][k] transposed
__device__ uint16_t g_Blo [(size_t)F1 * F0];

// ---------------- small helpers ---------------------------------------------
__device__ __forceinline__ uint32_t smem_u32(const void* p) {
    uint32_t a;
    asm("{ .reg .u64 t; cvta.to.shared.u64 t, %1; cvt.u32.u64 %0, t; }" : "=r"(a) : "l"(p));
    return a;
}
__device__ __forceinline__ void cp_async16(uint32_t dst, const void* src) {
    asm volatile("cp.async.cg.shared.global [%0], [%1], 16;" :: "r"(dst), "l"(src) : "memory");
}
__device__ __forceinline__ void cp_commit() {
    asm volatile("cp.async.commit_group;" ::: "memory");
}
__device__ __forceinline__ void mma_bf16(float* c, const uint32_t* a, const uint32_t* b) {
    asm volatile(
        "mma.sync.aligned.m16n8k16.row.col.f32.bf16.bf16.f32 "
        "{%0,%1,%2,%3}, {%4,%5,%6,%7}, {%8,%9}, {%0,%1,%2,%3};"
        : "+f"(c[0]), "+f"(c[1]), "+f"(c[2]), "+f"(c[3])
        : "r"(a[0]), "r"(a[1]), "r"(a[2]), "r"(a[3]), "r"(b[0]), "r"(b[1]));
}

// ---------------- CSR build --------------------------------------------------
__global__ void k_zero_cnt() {
    int i = blockIdx.x * blockDim.x + threadIdx.x;
    if (i < NNODES) g_cnt[i] = 0;
}

__global__ void k_count(const int* __restrict__ dst) {
    int e = blockIdx.x * blockDim.x + threadIdx.x;
    if (e < EDGES) {
        int d = dst[e];
        if ((unsigned)d < (unsigned)NNODES) atomicAdd(&g_cnt[d], 1);
    }
}

__global__ void k_scan() {
    __shared__ int part[1024];
    const int t  = threadIdx.x;
    const int CH = (NNODES + 1023) / 1024;
    int lo = t * CH;
    int hi = lo + CH; if (hi > NNODES) hi = NNODES;
    int s = 0;
    for (int i = lo; i < hi; i++) s += g_cnt[i];
    part[t] = s;
    __syncthreads();
    for (int d = 1; d < 1024; d <<= 1) {
        int add = (t >= d) ? part[t - d] : 0;
        __syncthreads();
        part[t] += add;
        __syncthreads();
    }
    int run = part[t] - s;
    for (int i = lo; i < hi; i++) {
        int c = g_cnt[i];
        g_off[i] = run;
        g_pos[i] = run;
        g_dis[i] = rsqrtf((float)(c + 1));
        run += c;
    }
    if (t == 1023) g_off[NNODES] = run;
}

__global__ void k_fill(const int* __restrict__ src,
                       const int* __restrict__ dst) {
    int e = blockIdx.x * blockDim.x + threadIdx.x;
    if (e < EDGES) {
        int d = dst[e];
        int s = src[e];
        if ((unsigned)d < (unsigned)NNODES && (unsigned)s < (unsigned)NNODES) {
            int p = atomicAdd(&g_pos[d], 1);
            g_srcs[p] = s;
        }
    }
}

// ---------------- prep: split x into bf16 hi/lo (padded rows zeroed) ---------
__global__ __launch_bounds__(256)
void k_prepA(const float* __restrict__ x) {
    size_t i = ((size_t)blockIdx.x * 256 + threadIdx.x) * 4;   // element index
    if (i >= (size_t)MPAD * F0) return;
    float4 v;
    if (i < (size_t)NNODES * F0) v = *(const float4*)(x + i);
    else v = make_float4(0.f, 0.f, 0.f, 0.f);
    uint16_t h[4], l[4];
    float vv[4] = {v.x, v.y, v.z, v.w};
#pragma unroll
    for (int j = 0; j < 4; j++) {
        __nv_bfloat16 hb = __float2bfloat16(vv[j]);
        __nv_bfloat16 lb = __float2bfloat16(vv[j] - __bfloat162float(hb));
        h[j] = *(uint16_t*)&hb;
        l[j] = *(uint16_t*)&lb;
    }
    *(uint64_t*)(g_Axhi + i) = *(uint64_t*)h;
    *(uint64_t*)(g_Axlo + i) = *(uint64_t*)l;
}

// split + transpose W1: [k][n] fp32 -> [n][k] bf16 hi/lo
__global__ void k_prepB(const float* __restrict__ W1) {
    int k = blockIdx.x;        // 0..511
    int n = threadIdx.x;       // 0..255
    float v = W1[k * F1 + n];
    __nv_bfloat16 hb = __float2bfloat16(v);
    __nv_bfloat16 lb = __float2bfloat16(v - __bfloat162float(hb));
    g_Bhi[(size_t)n * F0 + k] = *(uint16_t*)&hb;
    g_Blo[(size_t)n * F0 + k] = *(uint16_t*)&lb;
}

// ---------------- GEMM1 via mma.sync bf16-split ------------------------------
// C[M x 256] = A[M x 512] * B^T (B stored [n][k]).
// Grid: (2 n-tiles of 128, 782 m-tiles of 128). 256 threads, 8 warps.
// Warp grid 4(m) x 2(n): warp tile 32 x 64. k-step 32, cp.async double buffer.
// smem buffer layout (bytes): Ahi[128][40bf16] @0, Alo @10240, Bhi @20480, Blo @30720
#define GSTRIDE 40                // padded row stride in bf16 elements
#define BUFB 40960
#define G1_SMEM (2 * BUFB)

__global__ __launch_bounds__(256)
void k_mma1() {
    extern __shared__ char smem[];
    const uint32_t sb = smem_u32(smem);
    const int tid = threadIdx.x;
    const int lane = tid & 31;
    const int warp = tid >> 5;
    const int warp_m = warp & 3;        // 0..3
    const int warp_n = warp >> 2;       // 0..1
    const int m0 = blockIdx.y * 128;
    const int n0 = blockIdx.x * 128;

    // cp.async chunk mapping: 2048 16B-chunks per k-step, 8 per thread.
    // chunk c: sel = c/512 (0:Ahi 1:Alo 2:Bhi 3:Blo), row = (c%512)/4, part = c%4
    auto issue_load = [&](int it, int buf) {
        const int k0 = it * 32;
#pragma unroll
        for (int r = 0; r < 8; r++) {
            int c = tid + r * 256;
            int sel = c >> 9;
            int row = (c & 511) >> 2;
            int part = c & 3;
            uint32_t dst = sb + buf * BUFB + sel * 10240 + row * (GSTRIDE * 2) + part * 16;
            const uint16_t* srcbase;
            size_t gidx;
            if (sel < 2) {
                srcbase = sel ? g_Axlo : g_Axhi;
                gidx = (size_t)(m0 + row) * F0 + k0 + part * 8;
            } else {
                srcbase = (sel == 3) ? g_Blo : g_Bhi;
                gidx = (size_t)(n0 + row) * F0 + k0 + part * 8;
            }
            cp_async16(dst, srcbase + gidx);
        }
        cp_commit();
    };

    float acc[2][8][4];
#pragma unroll
    for (int mf = 0; mf < 2; mf++)
#pragma unroll
        for (int nf = 0; nf < 8; nf++)
#pragma unroll
            for (int j = 0; j < 4; j++) acc[mf][nf][j] = 0.f;

    issue_load(0, 0);
    issue_load(1, 1);

    const int arow = (lane >> 2);       // 0..7
    const int acol2 = (lane & 3) * 2;   // 0,2,4,6

    for (int it = 0; it < 16; it++) {
        if (it < 15) asm volatile("cp.async.wait_group 1;" ::: "memory");
        else         asm volatile("cp.async.wait_group 0;" ::: "memory");
        __syncthreads();

        const char* base = smem + (it & 1) * BUFB;
        const char* sAh = base;
        const char* sAl = base + 10240;
        const char* sBh = base + 20480;
        const char* sBl = base + 30720;

#pragma unroll
        for (int h = 0; h < 2; h++) {           // two k16 halves of the k32 tile
            uint32_t Ah[2][4], Al[2][4], Bh[8][2], Bl[8][2];
#pragma unroll
            for (int mf = 0; mf < 2; mf++) {
                int r = warp_m * 32 + mf * 16 + arow;
                int col = h * 16 + acol2;
                Ah[mf][0] = *(const uint32_t*)(sAh + r * 80 + col * 2);
                Ah[mf][1] = *(const uint32_t*)(sAh + (r + 8) * 80 + col * 2);
                Ah[mf][2] = *(const uint32_t*)(sAh + r * 80 + (col + 8) * 2);
                Ah[mf][3] = *(const uint32_t*)(sAh + (r + 8) * 80 + (col + 8) * 2);
                Al[mf][0] = *(const uint32_t*)(sAl + r * 80 + col * 2);
                Al[mf][1] = *(const uint32_t*)(sAl + (r + 8) * 80 + col * 2);
                Al[mf][2] = *(const uint32_t*)(sAl + r * 80 + (col + 8) * 2);
                Al[mf][3] = *(const uint32_t*)(sAl + (r + 8) * 80 + (col + 8) * 2);
            }
#pragma unroll
            for (int nf = 0; nf < 8; nf++) {
                int r = warp_n * 64 + nf * 8 + arow;
                int col = h * 16 + acol2;
                Bh[nf][0] = *(const uint32_t*)(sBh + r * 80 + col * 2);
                Bh[nf][1] = *(const uint32_t*)(sBh + r * 80 + (col + 8) * 2);
                Bl[nf][0] = *(const uint32_t*)(sBl + r * 80 + col * 2);
                Bl[nf][1] = *(const uint32_t*)(sBl + r * 80 + (col + 8) * 2);
            }
#pragma unroll
            for (int mf = 0; mf < 2; mf++)
#pragma unroll
                for (int nf = 0; nf < 8; nf++) {
                    mma_bf16(acc[mf][nf], Ah[mf], Bh[nf]);
                    mma_bf16(acc[mf][nf], Ah[mf], Bl[nf]);
                    mma_bf16(acc[mf][nf], Al[mf], Bh[nf]);
                }
        }
        __syncthreads();
        if (it + 2 < 16) issue_load(it + 2, it & 1);
    }

    // epilogue: write accumulators to g_h1
#pragma unroll
    for (int mf = 0; mf < 2; mf++) {
        int r0 = m0 + warp_m * 32 + mf * 16 + arow;
        int r1 = r0 + 8;
#pragma unroll
        for (int nf = 0; nf < 8; nf++) {
            int col = n0 + warp_n * 64 + nf * 8 + acol2;
            if (r0 < NNODES)
                *(float2*)(g_h1 + (size_t)r0 * F1 + col) = make_float2(acc[mf][nf][0], acc[mf][nf][1]);
            if (r1 < NNODES)
                *(float2*)(g_h1 + (size_t)r1 * F1 + col) = make_float2(acc[mf][nf][2], acc[mf][nf][3]);
        }
    }
}

// ---------------- agg1: h1a = relu( Â h1 + b1 ) ------------------------------
__global__ __launch_bounds__(64)
void k_agg1(const float* __restrict__ b1) {
    const int node = blockIdx.x;
    const int t = threadIdx.x;
    const float di = g_dis[node];
    const size_t col = (size_t)t * 4;

    float4 acc = *(const float4*)(g_h1 + (size_t)node * F1 + col);
    const float w0 = di * di;
    acc.x *= w0; acc.y *= w0; acc.z *= w0; acc.w *= w0;

    const int beg = g_off[node], end = g_off[node + 1];
    for (int e = beg; e < end; e++) {
        int s = g_srcs[e];
        float w = di * g_dis[s];
        float4 v = *(const float4*)(g_h1 + (size_t)s * F1 + col);
        acc.x += v.x * w; acc.y += v.y * w;
        acc.z += v.z * w; acc.w += v.w * w;
    }
    float4 bb = *(const float4*)(b1 + col);
    acc.x = fmaxf(acc.x + bb.x, 0.f);
    acc.y = fmaxf(acc.y + bb.y, 0.f);
    acc.z = fmaxf(acc.z + bb.z, 0.f);
    acc.w = fmaxf(acc.w + bb.w, 0.f);
    *(float4*)(g_h1a + (size_t)node * F1 + col) = acc;
}

// ---------------- GEMM2: g_h2 = h1a[100000x256] @ W2[256x40] -----------------
__global__ __launch_bounds__(256)
void k_gemm2(const float* __restrict__ W2) {
    __shared__ float Ws[F1 * 41];
    const int tid = threadIdx.x;
    for (int i = tid; i < F1 * F2; i += 256) {
        int k = i / F2, j = i % F2;
        Ws[k * 41 + j] = W2[i];
    }
    __syncthreads();
    const int warp = tid >> 5, lane = tid & 31;
    const int row = blockIdx.x * 8 + warp;
    if (row >= NNODES) return;

    float acc[F2];
#pragma unroll
    for (int j = 0; j < F2; j++) acc[j] = 0.f;

    for (int k = lane; k < F1; k += 32) {
        float a = g_h1a[(size_t)row * F1 + k];
        const float* w = &Ws[k * 41];
#pragma unroll
        for (int j = 0; j < F2; j++) acc[j] += a * w[j];
    }
#pragma unroll
    for (int j = 0; j < F2; j++) {
        float v = acc[j];
        v += __shfl_xor_sync(0xffffffffu, v, 16);
        v += __shfl_xor_sync(0xffffffffu, v, 8);
        v += __shfl_xor_sync(0xffffffffu, v, 4);
        v += __shfl_xor_sync(0xffffffffu, v, 2);
        v += __shfl_xor_sync(0xffffffffu, v, 1);
        acc[j] = v;
    }
    if (lane == 0) {
        float* out = g_h2 + (size_t)row * F2;
#pragma unroll
        for (int j = 0; j < F2; j++) out[j] = acc[j];
    }
}

// ---------------- agg2 + bias + log_softmax -> d_out -------------------------
__global__ __launch_bounds__(128)
void k_agg2(const float* __restrict__ b2, float* __restrict__ out) {
    const int node = blockIdx.x * 4 + (threadIdx.x >> 5);
    const int lane = threadIdx.x & 31;
    if (node >= NNODES) return;
    const float di = g_dis[node];

    float a0, a1 = 0.f;
    {
        const float w0 = di * di;
        const float* h = g_h2 + (size_t)node * F2;
        a0 = h[lane] * w0;
        if (lane < 8) a1 = h[32 + lane] * w0;
    }
    const int beg = g_off[node], end = g_off[node + 1];
    for (int e = beg; e < end; e++) {
        int s = g_srcs[e];
        float w = di * g_dis[s];
        const float* h = g_h2 + (size_t)s * F2;
        a0 += h[lane] * w;
        if (lane < 8) a1 += h[32 + lane] * w;
    }
    a0 += b2[lane];
    a1 = (lane < 8) ? (a1 + b2[32 + lane]) : -3.4e38f;

    float m = fmaxf(a0, a1);
    m = fmaxf(m, __shfl_xor_sync(0xffffffffu, m, 16));
    m = fmaxf(m, __shfl_xor_sync(0xffffffffu, m, 8));
    m = fmaxf(m, __shfl_xor_sync(0xffffffffu, m, 4));
    m = fmaxf(m, __shfl_xor_sync(0xffffffffu, m, 2));
    m = fmaxf(m, __shfl_xor_sync(0xffffffffu, m, 1));
    float s0 = expf(a0 - m) + ((lane < 8) ? expf(a1 - m) : 0.f);
    s0 += __shfl_xor_sync(0xffffffffu, s0, 16);
    s0 += __shfl_xor_sync(0xffffffffu, s0, 8);
    s0 += __shfl_xor_sync(0xffffffffu, s0, 4);
    s0 += __shfl_xor_sync(0xffffffffu, s0, 2);
    s0 += __shfl_xor_sync(0xffffffffu, s0, 1);
    const float ls = logf(s0) + m;

    float* o = out + (size_t)node * F2;
    o[lane] = a0 - ls;
    if (lane < 8) o[32 + lane] = a1 - ls;
}

// ---------------- launch -----------------------------------------------------
extern "C" void kernel_launch(void* const* d_in, const int* in_sizes, int n_in,
                              void* d_out, int out_size) {
    const float* x   = (const float*)d_in[0];
    const float* W1  = (const float*)d_in[1];
    const float* b1  = (const float*)d_in[2];
    const float* W2  = (const float*)d_in[3];
    const float* b2  = (const float*)d_in[4];
    const int*   ei  = (const int*)d_in[5];
    const int*   src = ei;
    const int*   dst = ei + EDGES;
    float* out = (float*)d_out;

    static int smem_set = 0;
    if (!smem_set) {
        cudaFuncSetAttribute(k_mma1, cudaFuncAttributeMaxDynamicSharedMemorySize, G1_SMEM);
        smem_set = 1;
    }

    k_zero_cnt<<<(NNODES + 255) / 256, 256>>>();
    k_count   <<<(EDGES + 255) / 256, 256>>>(dst);
    k_scan    <<<1, 1024>>>();
    k_fill    <<<(EDGES + 255) / 256, 256>>>(src, dst);

    k_prepA<<<(int)(((size_t)MPAD * F0 / 4 + 255) / 256), 256>>>(x);
    k_prepB<<<F0, F1>>>(W1);

    dim3 g1(2, MPAD / 128);
    k_mma1<<<g1, 256, G1_SMEM>>>();

    k_agg1  <<<NNODES, 64>>>(b1);
    k_gemm2 <<<(NNODES + 7) / 8, 256>>>(W2);
    k_agg2  <<<(NNODES + 3) / 4, 128>>>(b2, out);
}

// round 5
// speedup vs baseline: 1.3337x; 1.0688x over previous
#include <cuda_runtime.h>
#include <cuda_bf16.h>
#include <math.h>
#include <stdint.h>

// Problem constants (fixed by setup_inputs)
#define NNODES 100000
#define F0 512
#define F1 256
#define F2 40
#define EDGES 3200000

#define MPAD 100096            // 782 * 128

// ---------------- scratch (device globals; no allocations allowed) ----------
__device__ float g_dis[NNODES];            // deg_inv_sqrt
__device__ int   g_cnt[NNODES];            // in-degree (excl. self loop)
__device__ int   g_off[NNODES + 1];        // CSR offsets by dst
__device__ int   g_pos[NNODES];            // fill cursors
__device__ int   g_srcs[EDGES];            // CSR column (src) array
__device__ float g_h1 [(size_t)NNODES * F1];   // x @ W1
__device__ float g_h1a[(size_t)NNODES * F1];   // relu(agg(h1) + b1)
__device__ float g_h2 [(size_t)NNODES * F2];   // h1a @ W2

// bf16-split W1 for HMMA GEMM1 (transposed [n][k])
__device__ uint16_t g_Bhi [(size_t)F1 * F0];
__device__ uint16_t g_Blo [(size_t)F1 * F0];

// ---------------- small helpers ---------------------------------------------
__device__ __forceinline__ uint32_t smem_u32(const void* p) {
    uint32_t a;
    asm("{ .reg .u64 t; cvta.to.shared.u64 t, %1; cvt.u32.u64 %0, t; }" : "=r"(a) : "l"(p));
    return a;
}
__device__ __forceinline__ void cp_async16(uint32_t dst, const void* src) {
    asm volatile("cp.async.cg.shared.global [%0], [%1], 16;" :: "r"(dst), "l"(src) : "memory");
}
__device__ __forceinline__ void cp_commit() {
    asm volatile("cp.async.commit_group;" ::: "memory");
}
__device__ __forceinline__ void mma_bf16(float* c, const uint32_t* a, const uint32_t* b) {
    asm volatile(
        "mma.sync.aligned.m16n8k16.row.col.f32.bf16.bf16.f32 "
        "{%0,%1,%2,%3}, {%4,%5,%6,%7}, {%8,%9}, {%0,%1,%2,%3};"
        : "+f"(c[0]), "+f"(c[1]), "+f"(c[2]), "+f"(c[3])
        : "r"(a[0]), "r"(a[1]), "r"(a[2]), "r"(a[3]), "r"(b[0]), "r"(b[1]));
}
// split 8 floats into packed bf16 hi (uint4) and lo (uint4)
__device__ __forceinline__ void split8(const float* f, uint4& h, uint4& l) {
    uint16_t hh[8], ll[8];
#pragma unroll
    for (int j = 0; j < 8; j++) {
        __nv_bfloat16 hb = __float2bfloat16(f[j]);
        __nv_bfloat16 lb = __float2bfloat16(f[j] - __bfloat162float(hb));
        hh[j] = *(uint16_t*)&hb;
        ll[j] = *(uint16_t*)&lb;
    }
    h = *(uint4*)hh;
    l = *(uint4*)ll;
}

// ---------------- CSR build --------------------------------------------------
__global__ void k_zero_cnt() {
    int i = blockIdx.x * blockDim.x + threadIdx.x;
    if (i < NNODES) g_cnt[i] = 0;
}

__global__ void k_count(const int* __restrict__ dst) {
    int i = blockIdx.x * blockDim.x + threadIdx.x;      // i < EDGES/4
    int4 d = ((const int4*)dst)[i];
    if ((unsigned)d.x < (unsigned)NNODES) atomicAdd(&g_cnt[d.x], 1);
    if ((unsigned)d.y < (unsigned)NNODES) atomicAdd(&g_cnt[d.y], 1);
    if ((unsigned)d.z < (unsigned)NNODES) atomicAdd(&g_cnt[d.z], 1);
    if ((unsigned)d.w < (unsigned)NNODES) atomicAdd(&g_cnt[d.w], 1);
}

__global__ void k_scan() {
    __shared__ int part[1024];
    const int t  = threadIdx.x;
    const int CH = (NNODES + 1023) / 1024;
    int lo = t * CH;
    int hi = lo + CH; if (hi > NNODES) hi = NNODES;
    int s = 0;
    for (int i = lo; i < hi; i++) s += g_cnt[i];
    part[t] = s;
    __syncthreads();
    for (int d = 1; d < 1024; d <<= 1) {
        int add = (t >= d) ? part[t - d] : 0;
        __syncthreads();
        part[t] += add;
        __syncthreads();
    }
    int run = part[t] - s;
    for (int i = lo; i < hi; i++) {
        int c = g_cnt[i];
        g_off[i] = run;
        g_pos[i] = run;
        g_dis[i] = rsqrtf((float)(c + 1));
        run += c;
    }
    if (t == 1023) g_off[NNODES] = run;
}

__global__ void k_fill(const int* __restrict__ src,
                       const int* __restrict__ dst) {
    int i = blockIdx.x * blockDim.x + threadIdx.x;      // i < EDGES/4
    int4 d = ((const int4*)dst)[i];
    int4 s = ((const int4*)src)[i];
#pragma unroll
    for (int j = 0; j < 4; j++) {
        int dd = (&d.x)[j];
        int ss = (&s.x)[j];
        if ((unsigned)dd < (unsigned)NNODES && (unsigned)ss < (unsigned)NNODES) {
            int p = atomicAdd(&g_pos[dd], 1);
            g_srcs[p] = ss;
        }
    }
}

// split + transpose W1: [k][n] fp32 -> [n][k] bf16 hi/lo
__global__ void k_prepB(const float* __restrict__ W1) {
    int k = blockIdx.x;        // 0..511
    int n = threadIdx.x;       // 0..255
    float v = W1[k * F1 + n];
    __nv_bfloat16 hb = __float2bfloat16(v);
    __nv_bfloat16 lb = __float2bfloat16(v - __bfloat162float(hb));
    g_Bhi[(size_t)n * F0 + k] = *(uint16_t*)&hb;
    g_Blo[(size_t)n * F0 + k] = *(uint16_t*)&lb;
}

// ---------------- GEMM1 via mma.sync bf16-split, inline A conversion ---------
// C[M x 256] = A[M x 512] * B^T (B stored [n][k]).
// Grid: (2 n-tiles of 128, 782 m-tiles of 128). 256 threads, 8 warps.
// Warp grid 4(m) x 2(n): warp tile 32 x 64. k-step 32, double buffer.
// smem buffer layout (bytes): Ahi[128 rows x 80B] @0, Alo @10240,
//                             Bhi @20480, Blo @30720
#define BUFB 40960
#define G1_SMEM (2 * BUFB)

__global__ __launch_bounds__(256)
void k_mma1(const float* __restrict__ x) {
    extern __shared__ char smem[];
    const uint32_t sb = smem_u32(smem);
    const int tid = threadIdx.x;
    const int lane = tid & 31;
    const int warp = tid >> 5;
    const int warp_m = warp & 3;        // 0..3
    const int warp_n = warp >> 2;       // 0..1
    const int m0 = blockIdx.y * 128;
    const int n0 = blockIdx.x * 128;

    // ---- B loader: 1024 16B chunks per k-step, 4 per thread -----------------
    auto issue_B = [&](int it, int buf) {
        const int k0 = it * 32;
#pragma unroll
        for (int r = 0; r < 4; r++) {
            int c = tid + r * 256;
            int sel  = c >> 9;            // 0: Bhi, 1: Blo
            int row  = (c & 511) >> 2;
            int part = c & 3;
            uint32_t dstp = sb + buf * BUFB + 20480 + sel * 10240 + row * 80 + part * 16;
            const uint16_t* srcb = sel ? g_Blo : g_Bhi;
            cp_async16(dstp, srcb + (size_t)(n0 + row) * F0 + k0 + part * 8);
        }
        cp_commit();
    };

    // ---- A loader: fp32 from x, 16 floats per thread ------------------------
    const int arow_ld = tid >> 1;            // 0..127
    const int ahalf   = (tid & 1) * 16;      // k offset within step
    int grow = m0 + arow_ld;
    if (grow >= NNODES) grow = NNODES - 1;   // pad rows: duplicate (discarded)
    const float* aptr = x + (size_t)grow * F0 + ahalf;

    float areg[16];
    auto load_A = [&](int it) {
        const float4* p = (const float4*)(aptr + it * 32);
#pragma unroll
        for (int q = 0; q < 4; q++) *(float4*)(areg + q * 4) = p[q];
    };
    auto store_A = [&](int buf) {
        char* ahi = smem + buf * BUFB;
        char* alo = ahi + 10240;
        uint32_t soff = (uint32_t)arow_ld * 80 + (uint32_t)ahalf * 2;
        uint4 h0, l0, h1, l1;
        split8(areg,     h0, l0);
        split8(areg + 8, h1, l1);
        *(uint4*)(ahi + soff)      = h0;
        *(uint4*)(ahi + soff + 16) = h1;
        *(uint4*)(alo + soff)      = l0;
        *(uint4*)(alo + soff + 16) = l1;
    };

    float acc[2][8][4];
#pragma unroll
    for (int mf = 0; mf < 2; mf++)
#pragma unroll
        for (int nf = 0; nf < 8; nf++)
#pragma unroll
            for (int j = 0; j < 4; j++) acc[mf][nf][j] = 0.f;

    issue_B(0, 0);
    issue_B(1, 1);
    load_A(0);

    const int arow  = (lane >> 2);       // 0..7
    const int acol2 = (lane & 3) * 2;    // 0,2,4,6

    for (int it = 0; it < 16; it++) {
        const int buf = it & 1;
        store_A(buf);
        if (it < 15) asm volatile("cp.async.wait_group 1;" ::: "memory");
        else         asm volatile("cp.async.wait_group 0;" ::: "memory");
        __syncthreads();
        if (it + 1 < 16) load_A(it + 1);     // LDGs in flight during MMAs

        const char* base = smem + buf * BUFB;
        const char* sAh = base;
        const char* sAl = base + 10240;
        const char* sBh = base + 20480;
        const char* sBl = base + 30720;

#pragma unroll
        for (int h = 0; h < 2; h++) {        // two k16 halves of the k32 tile
            uint32_t Ah[2][4], Al[2][4], Bh[8][2], Bl[8][2];
#pragma unroll
            for (int mf = 0; mf < 2; mf++) {
                int r = warp_m * 32 + mf * 16 + arow;
                int col = h * 16 + acol2;
                Ah[mf][0] = *(const uint32_t*)(sAh + r * 80 + col * 2);
                Ah[mf][1] = *(const uint32_t*)(sAh + (r + 8) * 80 + col * 2);
                Ah[mf][2] = *(const uint32_t*)(sAh + r * 80 + (col + 8) * 2);
                Ah[mf][3] = *(const uint32_t*)(sAh + (r + 8) * 80 + (col + 8) * 2);
                Al[mf][0] = *(const uint32_t*)(sAl + r * 80 + col * 2);
                Al[mf][1] = *(const uint32_t*)(sAl + (r + 8) * 80 + col * 2);
                Al[mf][2] = *(const uint32_t*)(sAl + r * 80 + (col + 8) * 2);
                Al[mf][3] = *(const uint32_t*)(sAl + (r + 8) * 80 + (col + 8) * 2);
            }
#pragma unroll
            for (int nf = 0; nf < 8; nf++) {
                int r = warp_n * 64 + nf * 8 + arow;
                int col = h * 16 + acol2;
                Bh[nf][0] = *(const uint32_t*)(sBh + r * 80 + col * 2);
                Bh[nf][1] = *(const uint32_t*)(sBh + r * 80 + (col + 8) * 2);
                Bl[nf][0] = *(const uint32_t*)(sBl + r * 80 + col * 2);
                Bl[nf][1] = *(const uint32_t*)(sBl + r * 80 + (col + 8) * 2);
            }
#pragma unroll
            for (int mf = 0; mf < 2; mf++)
#pragma unroll
                for (int nf = 0; nf < 8; nf++) {
                    mma_bf16(acc[mf][nf], Ah[mf], Bh[nf]);
                    mma_bf16(acc[mf][nf], Ah[mf], Bl[nf]);
                    mma_bf16(acc[mf][nf], Al[mf], Bh[nf]);
                }
        }
        __syncthreads();
        if (it + 2 < 16) issue_B(it + 2, buf);
    }

    // epilogue: write accumulators to g_h1
#pragma unroll
    for (int mf = 0; mf < 2; mf++) {
        int r0 = m0 + warp_m * 32 + mf * 16 + arow;
        int r1 = r0 + 8;
#pragma unroll
        for (int nf = 0; nf < 8; nf++) {
            int col = n0 + warp_n * 64 + nf * 8 + acol2;
            if (r0 < NNODES)
                *(float2*)(g_h1 + (size_t)r0 * F1 + col) = make_float2(acc[mf][nf][0], acc[mf][nf][1]);
            if (r1 < NNODES)
                *(float2*)(g_h1 + (size_t)r1 * F1 + col) = make_float2(acc[mf][nf][2], acc[mf][nf][3]);
        }
    }
}

// ---------------- agg1: h1a = relu( Â h1 + b1 ) ------------------------------
__global__ __launch_bounds__(64)
void k_agg1(const float* __restrict__ b1) {
    const int node = blockIdx.x;
    const int t = threadIdx.x;
    const float di = g_dis[node];
    const size_t col = (size_t)t * 4;

    float4 acc = *(const float4*)(g_h1 + (size_t)node * F1 + col);
    const float w0 = di * di;
    acc.x *= w0; acc.y *= w0; acc.z *= w0; acc.w *= w0;

    const int beg = g_off[node], end = g_off[node + 1];
    for (int e = beg; e < end; e++) {
        int s = g_srcs[e];
        float w = di * g_dis[s];
        float4 v = *(const float4*)(g_h1 + (size_t)s * F1 + col);
        acc.x += v.x * w; acc.y += v.y * w;
        acc.z += v.z * w; acc.w += v.w * w;
    }
    float4 bb = *(const float4*)(b1 + col);
    acc.x = fmaxf(acc.x + bb.x, 0.f);
    acc.y = fmaxf(acc.y + bb.y, 0.f);
    acc.z = fmaxf(acc.z + bb.z, 0.f);
    acc.w = fmaxf(acc.w + bb.w, 0.f);
    __stcs((float4*)(g_h1a + (size_t)node * F1 + col), acc);   // evict-first
}

// ---------------- GEMM2: g_h2 = h1a[100000x256] @ W2[256x40] -----------------
__global__ __launch_bounds__(256)
void k_gemm2(const float* __restrict__ W2) {
    __shared__ float Ws[F1 * 41];
    const int tid = threadIdx.x;
    for (int i = tid; i < F1 * F2; i += 256) {
        int k = i / F2, j = i % F2;
        Ws[k * 41 + j] = W2[i];
    }
    __syncthreads();
    const int warp = tid >> 5, lane = tid & 31;
    const int row = blockIdx.x * 8 + warp;
    if (row >= NNODES) return;

    float acc[F2];
#pragma unroll
    for (int j = 0; j < F2; j++) acc[j] = 0.f;

    for (int k = lane; k < F1; k += 32) {
        float a = __ldcs(g_h1a + (size_t)row * F1 + k);        // read-once stream
        const float* w = &Ws[k * 41];
#pragma unroll
        for (int j = 0; j < F2; j++) acc[j] += a * w[j];
    }
#pragma unroll
    for (int j = 0; j < F2; j++) {
        float v = acc[j];
        v += __shfl_xor_sync(0xffffffffu, v, 16);
        v += __shfl_xor_sync(0xffffffffu, v, 8);
        v += __shfl_xor_sync(0xffffffffu, v, 4);
        v += __shfl_xor_sync(0xffffffffu, v, 2);
        v += __shfl_xor_sync(0xffffffffu, v, 1);
        acc[j] = v;
    }
    if (lane == 0) {
        float* out = g_h2 + (size_t)row * F2;
#pragma unroll
        for (int j = 0; j < F2; j++) out[j] = acc[j];
    }
}

// ---------------- agg2 + bias + log_softmax -> d_out -------------------------
__global__ __launch_bounds__(128)
void k_agg2(const float* __restrict__ b2, float* __restrict__ out) {
    const int node = blockIdx.x * 4 + (threadIdx.x >> 5);
    const int lane = threadIdx.x & 31;
    if (node >= NNODES) return;
    const float di = g_dis[node];

    float a0, a1 = 0.f;
    {
        const float w0 = di * di;
        const float* h = g_h2 + (size_t)node * F2;
        a0 = h[lane] * w0;
        if (lane < 8) a1 = h[32 + lane] * w0;
    }
    const int beg = g_off[node], end = g_off[node + 1];
    for (int e = beg; e < end; e++) {
        int s = g_srcs[e];
        float w = di * g_dis[s];
        const float* h = g_h2 + (size_t)s * F2;
        a0 += h[lane] * w;
        if (lane < 8) a1 += h[32 + lane] * w;
    }
    a0 += b2[lane];
    a1 = (lane < 8) ? (a1 + b2[32 + lane]) : -3.4e38f;

    float m = fmaxf(a0, a1);
    m = fmaxf(m, __shfl_xor_sync(0xffffffffu, m, 16));
    m = fmaxf(m, __shfl_xor_sync(0xffffffffu, m, 8));
    m = fmaxf(m, __shfl_xor_sync(0xffffffffu, m, 4));
    m = fmaxf(m, __shfl_xor_sync(0xffffffffu, m, 2));
    m = fmaxf(m, __shfl_xor_sync(0xffffffffu, m, 1));
    float s0 = expf(a0 - m) + ((lane < 8) ? expf(a1 - m) : 0.f);
    s0 += __shfl_xor_sync(0xffffffffu, s0, 16);
    s0 += __shfl_xor_sync(0xffffffffu, s0, 8);
    s0 += __shfl_xor_sync(0xffffffffu, s0, 4);
    s0 += __shfl_xor_sync(0xffffffffu, s0, 2);
    s0 += __shfl_xor_sync(0xffffffffu, s0, 1);
    const float ls = logf(s0) + m;

    float* o = out + (size_t)node * F2;
    __stcs(o + lane, a0 - ls);
    if (lane < 8) __stcs(o + 32 + lane, a1 - ls);
}

// ---------------- launch -----------------------------------------------------
extern "C" void kernel_launch(void* const* d_in, const int* in_sizes, int n_in,
                              void* d_out, int out_size) {
    const float* x   = (const float*)d_in[0];
    const float* W1  = (const float*)d_in[1];
    const float* b1  = (const float*)d_in[2];
    const float* W2  = (const float*)d_in[3];
    const float* b2  = (const float*)d_in[4];
    const int*   ei  = (const int*)d_in[5];
    const int*   src = ei;
    const int*   dst = ei + EDGES;
    float* out = (float*)d_out;

    static int smem_set = 0;
    if (!smem_set) {
        cudaFuncSetAttribute(k_mma1, cudaFuncAttributeMaxDynamicSharedMemorySize, G1_SMEM);
        smem_set = 1;
    }

    k_zero_cnt<<<(NNODES + 255) / 256, 256>>>();
    k_count   <<<(EDGES / 4 + 255) / 256, 256>>>(dst);
    k_scan    <<<1, 1024>>>();
    k_fill    <<<(EDGES / 4 + 255) / 256, 256>>>(src, dst);

    k_prepB<<<F0, F1>>>(W1);

    dim3 g1(2, MPAD / 128);
    k_mma1<<<g1, 256, G1_SMEM>>>(x);

    k_agg1  <<<NNODES, 64>>>(b1);
    k_gemm2 <<<(NNODES + 7) / 8, 256>>>(W2);
    k_agg2  <<<(NNODES + 3) / 4, 128>>>(b2, out);
}

// round 6
// speedup vs baseline: 1.3987x; 1.0487x over previous
#include <cuda_runtime.h>
#include <cuda_bf16.h>
#include <math.h>
#include <stdint.h>

// Problem constants (fixed by setup_inputs)
#define NNODES 100000
#define F0 512
#define F1 256
#define F2 40
#define EDGES 3200000

#define MPAD 100096            // 782 * 128

// ---------------- scratch (device globals; no allocations allowed) ----------
__device__ float g_dis[NNODES];            // deg_inv_sqrt
__device__ int   g_cnt[NNODES];            // in-degree (excl. self loop)
__device__ int   g_off[NNODES + 1];        // CSR offsets by dst
__device__ int   g_pos[NNODES];            // fill cursors
__device__ int   g_srcs[EDGES];            // CSR column (src) array
__device__ float g_w   [EDGES];            // per-edge dis[src]
__device__ float g_h1 [(size_t)NNODES * F1];   // x @ W1
__device__ float g_h1a[(size_t)NNODES * F1];   // relu(agg(h1) + b1)
__device__ float g_h2 [(size_t)NNODES * F2];   // h1a @ W2

// bf16-split W1 for HMMA GEMM1 (transposed [n][k])
__device__ uint16_t g_Bhi [(size_t)F1 * F0];
__device__ uint16_t g_Blo [(size_t)F1 * F0];

// ---------------- small helpers ---------------------------------------------
__device__ __forceinline__ uint32_t smem_u32(const void* p) {
    uint32_t a;
    asm("{ .reg .u64 t; cvta.to.shared.u64 t, %1; cvt.u32.u64 %0, t; }" : "=r"(a) : "l"(p));
    return a;
}
__device__ __forceinline__ void cp_async16(uint32_t dst, const void* src) {
    asm volatile("cp.async.cg.shared.global [%0], [%1], 16;" :: "r"(dst), "l"(src) : "memory");
}
__device__ __forceinline__ void cp_commit() {
    asm volatile("cp.async.commit_group;" ::: "memory");
}
__device__ __forceinline__ void mma_bf16(float* c, const uint32_t* a, const uint32_t* b) {
    asm volatile(
        "mma.sync.aligned.m16n8k16.row.col.f32.bf16.bf16.f32 "
        "{%0,%1,%2,%3}, {%4,%5,%6,%7}, {%8,%9}, {%0,%1,%2,%3};"
        : "+f"(c[0]), "+f"(c[1]), "+f"(c[2]), "+f"(c[3])
        : "r"(a[0]), "r"(a[1]), "r"(a[2]), "r"(a[3]), "r"(b[0]), "r"(b[1]));
}
__device__ __forceinline__ void ldm_x4(uint32_t& r0, uint32_t& r1, uint32_t& r2, uint32_t& r3,
                                       uint32_t addr) {
    asm volatile("ldmatrix.sync.aligned.m8n8.x4.shared.b16 {%0,%1,%2,%3}, [%4];"
                 : "=r"(r0), "=r"(r1), "=r"(r2), "=r"(r3) : "r"(addr));
}
// split 8 floats into packed bf16 hi (uint4) and lo (uint4)
__device__ __forceinline__ void split8(const float* f, uint4& h, uint4& l) {
    uint16_t hh[8], ll[8];
#pragma unroll
    for (int j = 0; j < 8; j++) {
        __nv_bfloat16 hb = __float2bfloat16(f[j]);
        __nv_bfloat16 lb = __float2bfloat16(f[j] - __bfloat162float(hb));
        hh[j] = *(uint16_t*)&hb;
        ll[j] = *(uint16_t*)&ll[j], ll[j] = *(uint16_t*)&lb;
    }
    h = *(uint4*)hh;
    l = *(uint4*)ll;
}

// ---------------- CSR build --------------------------------------------------
__global__ void k_zero_cnt() {
    int i = blockIdx.x * blockDim.x + threadIdx.x;
    if (i < NNODES) g_cnt[i] = 0;
}

__global__ void k_count(const int* __restrict__ dst) {
    int i = blockIdx.x * blockDim.x + threadIdx.x;      // i < EDGES/4
    int4 d = ((const int4*)dst)[i];
    if ((unsigned)d.x < (unsigned)NNODES) atomicAdd(&g_cnt[d.x], 1);
    if ((unsigned)d.y < (unsigned)NNODES) atomicAdd(&g_cnt[d.y], 1);
    if ((unsigned)d.z < (unsigned)NNODES) atomicAdd(&g_cnt[d.z], 1);
    if ((unsigned)d.w < (unsigned)NNODES) atomicAdd(&g_cnt[d.w], 1);
}

__global__ void k_scan() {
    __shared__ int part[1024];
    const int t  = threadIdx.x;
    const int CH = (NNODES + 1023) / 1024;
    int lo = t * CH;
    int hi = lo + CH; if (hi > NNODES) hi = NNODES;
    int s = 0;
    for (int i = lo; i < hi; i++) s += g_cnt[i];
    part[t] = s;
    __syncthreads();
    for (int d = 1; d < 1024; d <<= 1) {
        int add = (t >= d) ? part[t - d] : 0;
        __syncthreads();
        part[t] += add;
        __syncthreads();
    }
    int run = part[t] - s;
    for (int i = lo; i < hi; i++) {
        int c = g_cnt[i];
        g_off[i] = run;
        g_pos[i] = run;
        g_dis[i] = rsqrtf((float)(c + 1));
        run += c;
    }
    if (t == 1023) g_off[NNODES] = run;
}

__global__ void k_fill(const int* __restrict__ src,
                       const int* __restrict__ dst) {
    int i = blockIdx.x * blockDim.x + threadIdx.x;      // i < EDGES/4
    int4 d = ((const int4*)dst)[i];
    int4 s = ((const int4*)src)[i];
#pragma unroll
    for (int j = 0; j < 4; j++) {
        int dd = (&d.x)[j];
        int ss = (&s.x)[j];
        if ((unsigned)dd < (unsigned)NNODES && (unsigned)ss < (unsigned)NNODES) {
            int p = atomicAdd(&g_pos[dd], 1);
            g_srcs[p] = ss;
            g_w[p] = g_dis[ss];
        }
    }
}

// split + transpose W1: [k][n] fp32 -> [n][k] bf16 hi/lo
__global__ void k_prepB(const float* __restrict__ W1) {
    int k = blockIdx.x;        // 0..511
    int n = threadIdx.x;       // 0..255
    float v = W1[k * F1 + n];
    __nv_bfloat16 hb = __float2bfloat16(v);
    __nv_bfloat16 lb = __float2bfloat16(v - __bfloat162float(hb));
    g_Bhi[(size_t)n * F0 + k] = *(uint16_t*)&hb;
    g_Blo[(size_t)n * F0 + k] = *(uint16_t*)&lb;
}

// ---------------- GEMM1 via mma.sync bf16-split, inline A conversion ---------
// C[M x 256] = A[M x 512] * B^T (B stored [n][k]).
// Grid: (2 n-tiles of 128, 782 m-tiles of 128). 256 threads, 8 warps.
// Warp grid 4(m) x 2(n): warp tile 32 x 64. k-step 32, double buffer.
// smem buffer layout (bytes): Ahi[128 rows x 80B] @0, Alo @10240,
//                             Bhi @20480, Blo @30720
#define BUFB 40960
#define G1_SMEM (2 * BUFB)

__global__ __launch_bounds__(256)
void k_mma1(const float* __restrict__ x) {
    extern __shared__ char smem[];
    const uint32_t sb = smem_u32(smem);
    const int tid = threadIdx.x;
    const int lane = tid & 31;
    const int warp = tid >> 5;
    const int warp_m = warp & 3;        // 0..3
    const int warp_n = warp >> 2;       // 0..1
    const int m0 = blockIdx.y * 128;
    const int n0 = blockIdx.x * 128;

    // ---- B loader: 1024 16B chunks per k-step, 4 per thread -----------------
    auto issue_B = [&](int it, int buf) {
        const int k0 = it * 32;
#pragma unroll
        for (int r = 0; r < 4; r++) {
            int c = tid + r * 256;
            int sel  = c >> 9;            // 0: Bhi, 1: Blo
            int row  = (c & 511) >> 2;
            int part = c & 3;
            uint32_t dstp = sb + buf * BUFB + 20480 + sel * 10240 + row * 80 + part * 16;
            const uint16_t* srcb = sel ? g_Blo : g_Bhi;
            cp_async16(dstp, srcb + (size_t)(n0 + row) * F0 + k0 + part * 8);
        }
        cp_commit();
    };

    // ---- A loader: fp32 from x, 16 floats per thread ------------------------
    const int arow_ld = tid >> 1;            // 0..127
    const int ahalf   = (tid & 1) * 16;      // k offset within step
    int grow = m0 + arow_ld;
    if (grow >= NNODES) grow = NNODES - 1;   // pad rows: duplicate (discarded)
    const float* aptr = x + (size_t)grow * F0 + ahalf;

    float areg[16];
    auto load_A = [&](int it) {
        const float4* p = (const float4*)(aptr + it * 32);
#pragma unroll
        for (int q = 0; q < 4; q++) *(float4*)(areg + q * 4) = p[q];
    };
    auto store_A = [&](int buf) {
        char* ahi = smem + buf * BUFB;
        char* alo = ahi + 10240;
        uint32_t soff = (uint32_t)arow_ld * 80 + (uint32_t)ahalf * 2;
        uint4 h0, l0, h1, l1;
        split8(areg,     h0, l0);
        split8(areg + 8, h1, l1);
        *(uint4*)(ahi + soff)      = h0;
        *(uint4*)(ahi + soff + 16) = h1;
        *(uint4*)(alo + soff)      = l0;
        *(uint4*)(alo + soff + 16) = l1;
    };

    float acc[2][8][4];
#pragma unroll
    for (int mf = 0; mf < 2; mf++)
#pragma unroll
        for (int nf = 0; nf < 8; nf++)
#pragma unroll
            for (int j = 0; j < 4; j++) acc[mf][nf][j] = 0.f;

    issue_B(0, 0);
    issue_B(1, 1);
    load_A(0);

    const int arow  = (lane >> 2);       // 0..7
    const int acol2 = (lane & 3) * 2;    // 0,2,4,6

    // ldmatrix lane offsets
    // A x4: mats = (r..r+7,c), (r+8..r+15,c), (r..r+7,c+8), (r+8..,c+8)
    const uint32_t aOff = (uint32_t)((warp_m * 32 + (lane & 15)) * 80 + ((lane >> 4) & 1) * 16);
    // B x4: mats = (nf,k0-7), (nf,k8-15), (nf+1,k0-7), (nf+1,k8-15)
    const int bmat = lane >> 3;
    const uint32_t bOff = (uint32_t)((warp_n * 64 + (bmat >> 1) * 8 + (lane & 7)) * 80 + (bmat & 1) * 16);

    for (int it = 0; it < 16; it++) {
        const int buf = it & 1;
        store_A(buf);
        if (it < 15) asm volatile("cp.async.wait_group 1;" ::: "memory");
        else         asm volatile("cp.async.wait_group 0;" ::: "memory");
        __syncthreads();
        if (it + 1 < 16) load_A(it + 1);     // LDGs in flight during MMAs

        const uint32_t sAhi = sb + buf * BUFB;
        const uint32_t sAlo = sAhi + 10240;
        const uint32_t sBhi = sAhi + 20480;
        const uint32_t sBlo = sAhi + 30720;

#pragma unroll
        for (int h = 0; h < 2; h++) {        // two k16 halves of the k32 tile
            const uint32_t hB = (uint32_t)h * 32;     // 16 cols * 2B
            uint32_t Ah[2][4], Al[2][4], Bh[8][2], Bl[8][2];
#pragma unroll
            for (int mf = 0; mf < 2; mf++) {
                uint32_t off = aOff + (uint32_t)mf * (16 * 80) + hB;
                ldm_x4(Ah[mf][0], Ah[mf][1], Ah[mf][2], Ah[mf][3], sAhi + off);
                ldm_x4(Al[mf][0], Al[mf][1], Al[mf][2], Al[mf][3], sAlo + off);
            }
#pragma unroll
            for (int p = 0; p < 4; p++) {    // each x4 covers nf=2p, 2p+1
                uint32_t off = bOff + (uint32_t)p * (16 * 80) + hB;
                ldm_x4(Bh[2 * p][0], Bh[2 * p][1], Bh[2 * p + 1][0], Bh[2 * p + 1][1], sBhi + off);
                ldm_x4(Bl[2 * p][0], Bl[2 * p][1], Bl[2 * p + 1][0], Bl[2 * p + 1][1], sBlo + off);
            }
#pragma unroll
            for (int mf = 0; mf < 2; mf++)
#pragma unroll
                for (int nf = 0; nf < 8; nf++) {
                    mma_bf16(acc[mf][nf], Ah[mf], Bh[nf]);
                    mma_bf16(acc[mf][nf], Ah[mf], Bl[nf]);
                    mma_bf16(acc[mf][nf], Al[mf], Bh[nf]);
                }
        }
        __syncthreads();
        if (it + 2 < 16) issue_B(it + 2, buf);
    }

    // epilogue: write accumulators to g_h1
#pragma unroll
    for (int mf = 0; mf < 2; mf++) {
        int r0 = m0 + warp_m * 32 + mf * 16 + arow;
        int r1 = r0 + 8;
#pragma unroll
        for (int nf = 0; nf < 8; nf++) {
            int col = n0 + warp_n * 64 + nf * 8 + acol2;
            if (r0 < NNODES)
                *(float2*)(g_h1 + (size_t)r0 * F1 + col) = make_float2(acc[mf][nf][0], acc[mf][nf][1]);
            if (r1 < NNODES)
                *(float2*)(g_h1 + (size_t)r1 * F1 + col) = make_float2(acc[mf][nf][2], acc[mf][nf][3]);
        }
    }
}

// ---------------- agg1: h1a = relu( Â h1 + b1 ) ------------------------------
__global__ __launch_bounds__(64)
void k_agg1(const float* __restrict__ b1) {
    const int node = blockIdx.x;
    const int t = threadIdx.x;
    const float di = g_dis[node];
    const size_t col = (size_t)t * 4;

    float4 acc = *(const float4*)(g_h1 + (size_t)node * F1 + col);
    const float w0 = di * di;
    acc.x *= w0; acc.y *= w0; acc.z *= w0; acc.w *= w0;

    const int beg = g_off[node], end = g_off[node + 1];
#pragma unroll 4
    for (int e = beg; e < end; e++) {
        int s = g_srcs[e];
        float w = di * g_w[e];
        float4 v = *(const float4*)(g_h1 + (size_t)s * F1 + col);
        acc.x += v.x * w; acc.y += v.y * w;
        acc.z += v.z * w; acc.w += v.w * w;
    }
    float4 bb = *(const float4*)(b1 + col);
    acc.x = fmaxf(acc.x + bb.x, 0.f);
    acc.y = fmaxf(acc.y + bb.y, 0.f);
    acc.z = fmaxf(acc.z + bb.z, 0.f);
    acc.w = fmaxf(acc.w + bb.w, 0.f);
    __stcs((float4*)(g_h1a + (size_t)node * F1 + col), acc);   // evict-first
}

// ---------------- GEMM2: g_h2 = h1a[100000x256] @ W2[256x40] -----------------
__global__ __launch_bounds__(256)
void k_gemm2(const float* __restrict__ W2) {
    __shared__ float Ws[F1 * 41];
    const int tid = threadIdx.x;
    for (int i = tid; i < F1 * F2; i += 256) {
        int k = i / F2, j = i % F2;
        Ws[k * 41 + j] = W2[i];
    }
    __syncthreads();
    const int warp = tid >> 5, lane = tid & 31;
    const int row = blockIdx.x * 8 + warp;
    if (row >= NNODES) return;

    float acc[F2];
#pragma unroll
    for (int j = 0; j < F2; j++) acc[j] = 0.f;

    for (int k = lane; k < F1; k += 32) {
        float a = __ldcs(g_h1a + (size_t)row * F1 + k);        // read-once stream
        const float* w = &Ws[k * 41];
#pragma unroll
        for (int j = 0; j < F2; j++) acc[j] += a * w[j];
    }
#pragma unroll
    for (int j = 0; j < F2; j++) {
        float v = acc[j];
        v += __shfl_xor_sync(0xffffffffu, v, 16);
        v += __shfl_xor_sync(0xffffffffu, v, 8);
        v += __shfl_xor_sync(0xffffffffu, v, 4);
        v += __shfl_xor_sync(0xffffffffu, v, 2);
        v += __shfl_xor_sync(0xffffffffu, v, 1);
        acc[j] = v;
    }
    if (lane == 0) {
        float* out = g_h2 + (size_t)row * F2;
#pragma unroll
        for (int j = 0; j < F2; j++) out[j] = acc[j];
    }
}

// ---------------- agg2 + bias + log_softmax -> d_out -------------------------
__global__ __launch_bounds__(128)
void k_agg2(const float* __restrict__ b2, float* __restrict__ out) {
    const int node = blockIdx.x * 4 + (threadIdx.x >> 5);
    const int lane = threadIdx.x & 31;
    if (node >= NNODES) return;
    const float di = g_dis[node];

    float a0, a1 = 0.f;
    {
        const float w0 = di * di;
        const float* h = g_h2 + (size_t)node * F2;
        a0 = h[lane] * w0;
        if (lane < 8) a1 = h[32 + lane] * w0;
    }
    const int beg = g_off[node], end = g_off[node + 1];
#pragma unroll 4
    for (int e = beg; e < end; e++) {
        int s = g_srcs[e];
        float w = di * g_w[e];
        const float* h = g_h2 + (size_t)s * F2;
        a0 += h[lane] * w;
        if (lane < 8) a1 += h[32 + lane] * w;
    }
    a0 += b2[lane];
    a1 = (lane < 8) ? (a1 + b2[32 + lane]) : -3.4e38f;

    float m = fmaxf(a0, a1);
    m = fmaxf(m, __shfl_xor_sync(0xffffffffu, m, 16));
    m = fmaxf(m, __shfl_xor_sync(0xffffffffu, m, 8));
    m = fmaxf(m, __shfl_xor_sync(0xffffffffu, m, 4));
    m = fmaxf(m, __shfl_xor_sync(0xffffffffu, m, 2));
    m = fmaxf(m, __shfl_xor_sync(0xffffffffu, m, 1));
    float s0 = expf(a0 - m) + ((lane < 8) ? expf(a1 - m) : 0.f);
    s0 += __shfl_xor_sync(0xffffffffu, s0, 16);
    s0 += __shfl_xor_sync(0xffffffffu, s0, 8);
    s0 += __shfl_xor_sync(0xffffffffu, s0, 4);
    s0 += __shfl_xor_sync(0xffffffffu, s0, 2);
    s0 += __shfl_xor_sync(0xffffffffu, s0, 1);
    const float ls = logf(s0) + m;

    float* o = out + (size_t)node * F2;
    __stcs(o + lane, a0 - ls);
    if (lane < 8) __stcs(o + 32 + lane, a1 - ls);
}

// ---------------- launch -----------------------------------------------------
extern "C" void kernel_launch(void* const* d_in, const int* in_sizes, int n_in,
                              void* d_out, int out_size) {
    const float* x   = (const float*)d_in[0];
    const float* W1  = (const float*)d_in[1];
    const float* b1  = (const float*)d_in[2];
    const float* W2  = (const float*)d_in[3];
    const float* b2  = (const float*)d_in[4];
    const int*   ei  = (const int*)d_in[5];
    const int*   src = ei;
    const int*   dst = ei + EDGES;
    float* out = (float*)d_out;

    static int smem_set = 0;
    if (!smem_set) {
        cudaFuncSetAttribute(k_mma1, cudaFuncAttributeMaxDynamicSharedMemorySize, G1_SMEM);
        smem_set = 1;
    }

    k_zero_cnt<<<(NNODES + 255) / 256, 256>>>();
    k_count   <<<(EDGES / 4 + 255) / 256, 256>>>(dst);
    k_scan    <<<1, 1024>>>();
    k_fill    <<<(EDGES / 4 + 255) / 256, 256>>>(src, dst);

    k_prepB<<<F0, F1>>>(W1);

    dim3 g1(2, MPAD / 128);
    k_mma1<<<g1, 256, G1_SMEM>>>(x);

    k_agg1  <<<NNODES, 64>>>(b1);
    k_gemm2 <<<(NNODES + 7) / 8, 256>>>(W2);
    k_agg2  <<<(NNODES + 3) / 4, 128>>>(b2, out);
}

// round 7
// speedup vs baseline: 1.5193x; 1.0863x over previous
#include <cuda_runtime.h>
#include <cuda_bf16.h>
#include <cuda_fp16.h>
#include <math.h>
#include <stdint.h>

// Problem constants (fixed by setup_inputs)
#define NNODES 100000
#define F0 512
#define F1 256
#define F2 40
#define EDGES 3200000

#define MPAD 100096            // 782 * 128

// ---------------- scratch (device globals; no allocations allowed) ----------
__device__ float g_dis[NNODES];            // deg_inv_sqrt
__device__ int   g_cnt[NNODES];            // in-degree (excl. self loop)
__device__ int   g_off[NNODES + 1];        // CSR offsets by dst
__device__ int   g_pos[NNODES];            // fill cursors
__device__ int   g_srcs[EDGES];            // CSR column (src) array
__device__ float g_w   [EDGES];            // per-edge dis[src]
__device__ float g_h1 [(size_t)NNODES * F1];   // x @ W1
__device__ float g_h1a[(size_t)NNODES * F1];   // relu(agg(h1) + b1)
__device__ float g_h2 [(size_t)NNODES * F2];   // h1a @ W2

// fp16-split W1 for HMMA GEMM1 (transposed [n][k])
__device__ uint16_t g_Bhi [(size_t)F1 * F0];
__device__ uint16_t g_Blo [(size_t)F1 * F0];

// ---------------- small helpers ---------------------------------------------
__device__ __forceinline__ uint32_t smem_u32(const void* p) {
    uint32_t a;
    asm("{ .reg .u64 t; cvta.to.shared.u64 t, %1; cvt.u32.u64 %0, t; }" : "=r"(a) : "l"(p));
    return a;
}
__device__ __forceinline__ void cp_async16(uint32_t dst, const void* src) {
    asm volatile("cp.async.cg.shared.global [%0], [%1], 16;" :: "r"(dst), "l"(src) : "memory");
}
__device__ __forceinline__ void cp_commit() {
    asm volatile("cp.async.commit_group;" ::: "memory");
}
__device__ __forceinline__ void mma_fp16(float* c, const uint32_t* a, const uint32_t* b) {
    asm volatile(
        "mma.sync.aligned.m16n8k16.row.col.f32.f16.f16.f32 "
        "{%0,%1,%2,%3}, {%4,%5,%6,%7}, {%8,%9}, {%0,%1,%2,%3};"
        : "+f"(c[0]), "+f"(c[1]), "+f"(c[2]), "+f"(c[3])
        : "r"(a[0]), "r"(a[1]), "r"(a[2]), "r"(a[3]), "r"(b[0]), "r"(b[1]));
}
__device__ __forceinline__ void ldm_x4(uint32_t& r0, uint32_t& r1, uint32_t& r2, uint32_t& r3,
                                       uint32_t addr) {
    asm volatile("ldmatrix.sync.aligned.m8n8.x4.shared.b16 {%0,%1,%2,%3}, [%4];"
                 : "=r"(r0), "=r"(r1), "=r"(r2), "=r"(r3) : "r"(addr));
}
// convert 8 floats to packed fp16 (uint4)
__device__ __forceinline__ void cvt8(const float* f, uint4& h) {
    uint16_t hh[8];
#pragma unroll
    for (int j = 0; j < 8; j++) {
        __half hb = __float2half_rn(f[j]);
        hh[j] = *(uint16_t*)&hb;
    }
    h = *(uint4*)hh;
}

// ---------------- CSR build --------------------------------------------------
__global__ void k_count(const int* __restrict__ dst) {
    int i = blockIdx.x * blockDim.x + threadIdx.x;      // i < EDGES/4
    int4 d = ((const int4*)dst)[i];
    if ((unsigned)d.x < (unsigned)NNODES) atomicAdd(&g_cnt[d.x], 1);
    if ((unsigned)d.y < (unsigned)NNODES) atomicAdd(&g_cnt[d.y], 1);
    if ((unsigned)d.z < (unsigned)NNODES) atomicAdd(&g_cnt[d.z], 1);
    if ((unsigned)d.w < (unsigned)NNODES) atomicAdd(&g_cnt[d.w], 1);
}

__global__ void k_scan() {
    __shared__ int part[1024];
    const int t  = threadIdx.x;
    const int CH = (NNODES + 1023) / 1024;
    int lo = t * CH;
    int hi = lo + CH; if (hi > NNODES) hi = NNODES;
    int s = 0;
    for (int i = lo; i < hi; i++) s += g_cnt[i];
    part[t] = s;
    __syncthreads();
    for (int d = 1; d < 1024; d <<= 1) {
        int add = (t >= d) ? part[t - d] : 0;
        __syncthreads();
        part[t] += add;
        __syncthreads();
    }
    int run = part[t] - s;
    for (int i = lo; i < hi; i++) {
        int c = g_cnt[i];
        g_off[i] = run;
        g_pos[i] = run;
        g_dis[i] = rsqrtf((float)(c + 1));
        run += c;
    }
    if (t == 1023) g_off[NNODES] = run;
}

__global__ void k_fill(const int* __restrict__ src,
                       const int* __restrict__ dst) {
    int i = blockIdx.x * blockDim.x + threadIdx.x;      // i < EDGES/4
    int4 d = ((const int4*)dst)[i];
    int4 s = ((const int4*)src)[i];
#pragma unroll
    for (int j = 0; j < 4; j++) {
        int dd = (&d.x)[j];
        int ss = (&s.x)[j];
        if ((unsigned)dd < (unsigned)NNODES && (unsigned)ss < (unsigned)NNODES) {
            int p = atomicAdd(&g_pos[dd], 1);
            g_srcs[p] = ss;
            g_w[p] = g_dis[ss];
        }
    }
}

// split + transpose W1: [k][n] fp32 -> [n][k] fp16 hi/lo
__global__ void k_prepB(const float* __restrict__ W1) {
    int k = blockIdx.x;        // 0..511
    int n = threadIdx.x;       // 0..255
    float v = W1[k * F1 + n];
    __half hb = __float2half_rn(v);
    __half lb = __float2half_rn(v - __half2float(hb));
    g_Bhi[(size_t)n * F0 + k] = *(uint16_t*)&hb;
    g_Blo[(size_t)n * F0 + k] = *(uint16_t*)&lb;
}

// ---------------- GEMM1 via mma.sync fp16, split-B ---------------------------
// C[M x 256] = A[M x 512] * B^T (B stored [n][k]); A cast to fp16,
// B = Bh + Bl (fp16 split): C = Ah*Bh + Ah*Bl  (2 MMAs, err ~2^-12 rms).
// Grid: (2 n-tiles of 128, 782 m-tiles of 128). 256 threads, 8 warps.
// Warp grid 4(m) x 2(n): warp tile 32 x 64. k-step 32, double buffer.
// smem buffer layout (bytes): Ah[128 rows x 80B] @0, Bhi @10240, Blo @20480
#define BUFB 30720
#define G1_SMEM (2 * BUFB)

__global__ __launch_bounds__(256)
void k_mma1(const float* __restrict__ x) {
    extern __shared__ char smem[];
    const uint32_t sb = smem_u32(smem);
    const int tid = threadIdx.x;
    const int lane = tid & 31;
    const int warp = tid >> 5;
    const int warp_m = warp & 3;        // 0..3
    const int warp_n = warp >> 2;       // 0..1
    const int m0 = blockIdx.y * 128;
    const int n0 = blockIdx.x * 128;

    // ---- B loader: 1024 16B chunks per k-step, 4 per thread -----------------
    auto issue_B = [&](int it, int buf) {
        const int k0 = it * 32;
#pragma unroll
        for (int r = 0; r < 4; r++) {
            int c = tid + r * 256;
            int sel  = c >> 9;            // 0: Bhi, 1: Blo
            int row  = (c & 511) >> 2;
            int part = c & 3;
            uint32_t dstp = sb + buf * BUFB + 10240 + sel * 10240 + row * 80 + part * 16;
            const uint16_t* srcb = sel ? g_Blo : g_Bhi;
            cp_async16(dstp, srcb + (size_t)(n0 + row) * F0 + k0 + part * 8);
        }
        cp_commit();
    };

    // ---- A loader: fp32 from x, 16 floats per thread ------------------------
    const int arow_ld = tid >> 1;            // 0..127
    const int ahalf   = (tid & 1) * 16;      // k offset within step
    int grow = m0 + arow_ld;
    if (grow >= NNODES) grow = NNODES - 1;   // pad rows: duplicate (discarded)
    const float* aptr = x + (size_t)grow * F0 + ahalf;

    float areg[16];
    auto load_A = [&](int it) {
        const float4* p = (const float4*)(aptr + it * 32);
#pragma unroll
        for (int q = 0; q < 4; q++) *(float4*)(areg + q * 4) = p[q];
    };
    auto store_A = [&](int buf) {
        char* ahi = smem + buf * BUFB;
        uint32_t soff = (uint32_t)arow_ld * 80 + (uint32_t)ahalf * 2;
        uint4 h0, h1;
        cvt8(areg,     h0);
        cvt8(areg + 8, h1);
        *(uint4*)(ahi + soff)      = h0;
        *(uint4*)(ahi + soff + 16) = h1;
    };

    float acc[2][8][4];
#pragma unroll
    for (int mf = 0; mf < 2; mf++)
#pragma unroll
        for (int nf = 0; nf < 8; nf++)
#pragma unroll
            for (int j = 0; j < 4; j++) acc[mf][nf][j] = 0.f;

    issue_B(0, 0);
    issue_B(1, 1);
    load_A(0);

    const int arow  = (lane >> 2);       // 0..7
    const int acol2 = (lane & 3) * 2;    // 0,2,4,6

    // ldmatrix lane offsets
    const uint32_t aOff = (uint32_t)((warp_m * 32 + (lane & 15)) * 80 + ((lane >> 4) & 1) * 16);
    const int bmat = lane >> 3;
    const uint32_t bOff = (uint32_t)((warp_n * 64 + (bmat >> 1) * 8 + (lane & 7)) * 80 + (bmat & 1) * 16);

    for (int it = 0; it < 16; it++) {
        const int buf = it & 1;
        store_A(buf);
        if (it < 15) asm volatile("cp.async.wait_group 1;" ::: "memory");
        else         asm volatile("cp.async.wait_group 0;" ::: "memory");
        __syncthreads();
        if (it + 1 < 16) load_A(it + 1);     // LDGs in flight during MMAs

        const uint32_t sAhi = sb + buf * BUFB;
        const uint32_t sBhi = sAhi + 10240;
        const uint32_t sBlo = sAhi + 20480;

#pragma unroll
        for (int h = 0; h < 2; h++) {        // two k16 halves of the k32 tile
            const uint32_t hB = (uint32_t)h * 32;     // 16 cols * 2B
            uint32_t Ah[2][4], Bh[8][2], Bl[8][2];
#pragma unroll
            for (int mf = 0; mf < 2; mf++) {
                uint32_t off = aOff + (uint32_t)mf * (16 * 80) + hB;
                ldm_x4(Ah[mf][0], Ah[mf][1], Ah[mf][2], Ah[mf][3], sAhi + off);
            }
#pragma unroll
            for (int p = 0; p < 4; p++) {    // each x4 covers nf=2p, 2p+1
                uint32_t off = bOff + (uint32_t)p * (16 * 80) + hB;
                ldm_x4(Bh[2 * p][0], Bh[2 * p][1], Bh[2 * p + 1][0], Bh[2 * p + 1][1], sBhi + off);
                ldm_x4(Bl[2 * p][0], Bl[2 * p][1], Bl[2 * p + 1][0], Bl[2 * p + 1][1], sBlo + off);
            }
#pragma unroll
            for (int mf = 0; mf < 2; mf++)
#pragma unroll
                for (int nf = 0; nf < 8; nf++) {
                    mma_fp16(acc[mf][nf], Ah[mf], Bh[nf]);
                    mma_fp16(acc[mf][nf], Ah[mf], Bl[nf]);
                }
        }
        __syncthreads();
        if (it + 2 < 16) issue_B(it + 2, buf);
    }

    // epilogue: write accumulators to g_h1
#pragma unroll
    for (int mf = 0; mf < 2; mf++) {
        int r0 = m0 + warp_m * 32 + mf * 16 + arow;
        int r1 = r0 + 8;
#pragma unroll
        for (int nf = 0; nf < 8; nf++) {
            int col = n0 + warp_n * 64 + nf * 8 + acol2;
            if (r0 < NNODES)
                *(float2*)(g_h1 + (size_t)r0 * F1 + col) = make_float2(acc[mf][nf][0], acc[mf][nf][1]);
            if (r1 < NNODES)
                *(float2*)(g_h1 + (size_t)r1 * F1 + col) = make_float2(acc[mf][nf][2], acc[mf][nf][3]);
        }
    }
}

// ---------------- agg1: h1a = relu( Â h1 + b1 ) ------------------------------
__global__ __launch_bounds__(64)
void k_agg1(const float* __restrict__ b1) {
    const int node = blockIdx.x;
    const int t = threadIdx.x;
    const float di = g_dis[node];
    const size_t col = (size_t)t * 4;

    float4 acc = *(const float4*)(g_h1 + (size_t)node * F1 + col);
    const float w0 = di * di;
    acc.x *= w0; acc.y *= w0; acc.z *= w0; acc.w *= w0;

    const int beg = g_off[node], end = g_off[node + 1];
#pragma unroll 4
    for (int e = beg; e < end; e++) {
        int s = g_srcs[e];
        float w = di * g_w[e];
        float4 v = *(const float4*)(g_h1 + (size_t)s * F1 + col);
        acc.x += v.x * w; acc.y += v.y * w;
        acc.z += v.z * w; acc.w += v.w * w;
    }
    float4 bb = *(const float4*)(b1 + col);
    acc.x = fmaxf(acc.x + bb.x, 0.f);
    acc.y = fmaxf(acc.y + bb.y, 0.f);
    acc.z = fmaxf(acc.z + bb.z, 0.f);
    acc.w = fmaxf(acc.w + bb.w, 0.f);
    __stcs((float4*)(g_h1a + (size_t)node * F1 + col), acc);   // evict-first
}

// ---------------- GEMM2: g_h2 = h1a[100000x256] @ W2[256x40] -----------------
__global__ __launch_bounds__(256)
void k_gemm2(const float* __restrict__ W2) {
    __shared__ float Ws[F1 * 41];
    const int tid = threadIdx.x;
    for (int i = tid; i < F1 * F2; i += 256) {
        int k = i / F2, j = i % F2;
        Ws[k * 41 + j] = W2[i];
    }
    __syncthreads();
    const int warp = tid >> 5, lane = tid & 31;
    const int row = blockIdx.x * 8 + warp;
    if (row >= NNODES) return;

    float acc[F2];
#pragma unroll
    for (int j = 0; j < F2; j++) acc[j] = 0.f;

    for (int k = lane; k < F1; k += 32) {
        float a = __ldcs(g_h1a + (size_t)row * F1 + k);        // read-once stream
        const float* w = &Ws[k * 41];
#pragma unroll
        for (int j = 0; j < F2; j++) acc[j] += a * w[j];
    }
#pragma unroll
    for (int j = 0; j < F2; j++) {
        float v = acc[j];
        v += __shfl_xor_sync(0xffffffffu, v, 16);
        v += __shfl_xor_sync(0xffffffffu, v, 8);
        v += __shfl_xor_sync(0xffffffffu, v, 4);
        v += __shfl_xor_sync(0xffffffffu, v, 2);
        v += __shfl_xor_sync(0xffffffffu, v, 1);
        acc[j] = v;
    }
    if (lane == 0) {
        float* out = g_h2 + (size_t)row * F2;
#pragma unroll
        for (int j = 0; j < F2; j++) out[j] = acc[j];
    }
}

// ---------------- agg2 + bias + log_softmax -> d_out -------------------------
__global__ __launch_bounds__(128)
void k_agg2(const float* __restrict__ b2, float* __restrict__ out) {
    const int node = blockIdx.x * 4 + (threadIdx.x >> 5);
    const int lane = threadIdx.x & 31;
    if (node >= NNODES) return;
    const float di = g_dis[node];

    float a0, a1 = 0.f;
    {
        const float w0 = di * di;
        const float* h = g_h2 + (size_t)node * F2;
        a0 = h[lane] * w0;
        if (lane < 8) a1 = h[32 + lane] * w0;
    }
    const int beg = g_off[node], end = g_off[node + 1];
#pragma unroll 4
    for (int e = beg; e < end; e++) {
        int s = g_srcs[e];
        float w = di * g_w[e];
        const float* h = g_h2 + (size_t)s * F2;
        a0 += h[lane] * w;
        if (lane < 8) a1 += h[32 + lane] * w;
    }
    a0 += b2[lane];
    a1 = (lane < 8) ? (a1 + b2[32 + lane]) : -3.4e38f;

    float m = fmaxf(a0, a1);
    m = fmaxf(m, __shfl_xor_sync(0xffffffffu, m, 16));
    m = fmaxf(m, __shfl_xor_sync(0xffffffffu, m, 8));
    m = fmaxf(m, __shfl_xor_sync(0xffffffffu, m, 4));
    m = fmaxf(m, __shfl_xor_sync(0xffffffffu, m, 2));
    m = fmaxf(m, __shfl_xor_sync(0xffffffffu, m, 1));
    float s0 = expf(a0 - m) + ((lane < 8) ? expf(a1 - m) : 0.f);
    s0 += __shfl_xor_sync(0xffffffffu, s0, 16);
    s0 += __shfl_xor_sync(0xffffffffu, s0, 8);
    s0 += __shfl_xor_sync(0xffffffffu, s0, 4);
    s0 += __shfl_xor_sync(0xffffffffu, s0, 2);
    s0 += __shfl_xor_sync(0xffffffffu, s0, 1);
    const float ls = logf(s0) + m;

    float* o = out + (size_t)node * F2;
    __stcs(o + lane, a0 - ls);
    if (lane < 8) __stcs(o + 32 + lane, a1 - ls);
}

// ---------------- launch -----------------------------------------------------
extern "C" void kernel_launch(void* const* d_in, const int* in_sizes, int n_in,
                              void* d_out, int out_size) {
    const float* x   = (const float*)d_in[0];
    const float* W1  = (const float*)d_in[1];
    const float* b1  = (const float*)d_in[2];
    const float* W2  = (const float*)d_in[3];
    const float* b2  = (const float*)d_in[4];
    const int*   ei  = (const int*)d_in[5];
    const int*   src = ei;
    const int*   dst = ei + EDGES;
    float* out = (float*)d_out;

    static void* cnt_addr = nullptr;
    if (!cnt_addr) {
        cudaFuncSetAttribute(k_mma1, cudaFuncAttributeMaxDynamicSharedMemorySize, G1_SMEM);
        cudaGetSymbolAddress(&cnt_addr, g_cnt);
    }

    cudaMemsetAsync(cnt_addr, 0, NNODES * sizeof(int));
    k_count   <<<(EDGES / 4 + 255) / 256, 256>>>(dst);
    k_scan    <<<1, 1024>>>();
    k_fill    <<<(EDGES / 4 + 255) / 256, 256>>>(src, dst);

    k_prepB<<<F0, F1>>>(W1);

    dim3 g1(2, MPAD / 128);
    k_mma1<<<g1, 256, G1_SMEM>>>(x);

    k_agg1  <<<NNODES, 64>>>(b1);
    k_gemm2 <<<(NNODES + 7) / 8, 256>>>(W2);
    k_agg2  <<<(NNODES + 3) / 4, 128>>>(b2, out);
}

// round 8
// speedup vs baseline: 1.6708x; 1.0997x over previous
#include <cuda_runtime.h>
#include <cuda_bf16.h>
#include <cuda_fp16.h>
#include <math.h>
#include <stdint.h>

// Problem constants (fixed by setup_inputs)
#define NNODES 100000
#define F0 512
#define F1 256
#define F2 40
#define EDGES 3200000

#define MPAD 100096            // 782 * 128

// ---------------- scratch (device globals; no allocations allowed) ----------
__device__ float g_dis[NNODES];            // deg_inv_sqrt
__device__ int   g_cnt[NNODES];            // in-degree (excl. self loop)
__device__ int   g_off[NNODES + 1];        // CSR offsets by dst
__device__ int   g_pos[NNODES];            // fill cursors
__device__ int2  g_edge[EDGES];            // packed (src, dis[src] bits)
__device__ uint16_t g_h1h[(size_t)MPAD * F1];   // x @ W1   (fp16)
__device__ float g_h1a[(size_t)NNODES * F1];    // relu(agg(h1) + b1)
__device__ float g_h2 [(size_t)NNODES * F2];    // h1a @ W2

// fp16-split W1 for HMMA GEMM1 (transposed [n][k])
__device__ uint16_t g_Bhi [(size_t)F1 * F0];
__device__ uint16_t g_Blo [(size_t)F1 * F0];

// ---------------- small helpers ---------------------------------------------
__device__ __forceinline__ uint32_t smem_u32(const void* p) {
    uint32_t a;
    asm("{ .reg .u64 t; cvta.to.shared.u64 t, %1; cvt.u32.u64 %0, t; }" : "=r"(a) : "l"(p));
    return a;
}
__device__ __forceinline__ void cp_async16(uint32_t dst, const void* src) {
    asm volatile("cp.async.cg.shared.global [%0], [%1], 16;" :: "r"(dst), "l"(src) : "memory");
}
__device__ __forceinline__ void cp_commit() {
    asm volatile("cp.async.commit_group;" ::: "memory");
}
__device__ __forceinline__ void mma_fp16(float* c, const uint32_t* a, const uint32_t* b) {
    asm volatile(
        "mma.sync.aligned.m16n8k16.row.col.f32.f16.f16.f32 "
        "{%0,%1,%2,%3}, {%4,%5,%6,%7}, {%8,%9}, {%0,%1,%2,%3};"
        : "+f"(c[0]), "+f"(c[1]), "+f"(c[2]), "+f"(c[3])
        : "r"(a[0]), "r"(a[1]), "r"(a[2]), "r"(a[3]), "r"(b[0]), "r"(b[1]));
}
__device__ __forceinline__ void ldm_x4(uint32_t& r0, uint32_t& r1, uint32_t& r2, uint32_t& r3,
                                       uint32_t addr) {
    asm volatile("ldmatrix.sync.aligned.m8n8.x4.shared.b16 {%0,%1,%2,%3}, [%4];"
                 : "=r"(r0), "=r"(r1), "=r"(r2), "=r"(r3) : "r"(addr));
}
// convert 8 floats to packed fp16 (uint4)
__device__ __forceinline__ void cvt8(const float* f, uint4& h) {
    uint16_t hh[8];
#pragma unroll
    for (int j = 0; j < 8; j++) {
        __half hb = __float2half_rn(f[j]);
        hh[j] = *(uint16_t*)&hb;
    }
    h = *(uint4*)hh;
}

// ---------------- CSR build --------------------------------------------------
__global__ void k_count(const int* __restrict__ dst) {
    int i = blockIdx.x * blockDim.x + threadIdx.x;      // i < EDGES/4
    int4 d = ((const int4*)dst)[i];
    if ((unsigned)d.x < (unsigned)NNODES) atomicAdd(&g_cnt[d.x], 1);
    if ((unsigned)d.y < (unsigned)NNODES) atomicAdd(&g_cnt[d.y], 1);
    if ((unsigned)d.z < (unsigned)NNODES) atomicAdd(&g_cnt[d.z], 1);
    if ((unsigned)d.w < (unsigned)NNODES) atomicAdd(&g_cnt[d.w], 1);
}

__global__ void k_scan() {
    __shared__ int part[1024];
    const int t  = threadIdx.x;
    const int CH = (NNODES + 1023) / 1024;
    int lo = t * CH;
    int hi = lo + CH; if (hi > NNODES) hi = NNODES;
    int s = 0;
    for (int i = lo; i < hi; i++) s += g_cnt[i];
    part[t] = s;
    __syncthreads();
    for (int d = 1; d < 1024; d <<= 1) {
        int add = (t >= d) ? part[t - d] : 0;
        __syncthreads();
        part[t] += add;
        __syncthreads();
    }
    int run = part[t] - s;
    for (int i = lo; i < hi; i++) {
        int c = g_cnt[i];
        g_off[i] = run;
        g_pos[i] = run;
        g_dis[i] = rsqrtf((float)(c + 1));
        run += c;
    }
    if (t == 1023) g_off[NNODES] = run;
}

__global__ void k_fill(const int* __restrict__ src,
                       const int* __restrict__ dst) {
    int i = blockIdx.x * blockDim.x + threadIdx.x;      // i < EDGES/4
    int4 d = ((const int4*)dst)[i];
    int4 s = ((const int4*)src)[i];
#pragma unroll
    for (int j = 0; j < 4; j++) {
        int dd = (&d.x)[j];
        int ss = (&s.x)[j];
        if ((unsigned)dd < (unsigned)NNODES && (unsigned)ss < (unsigned)NNODES) {
            int p = atomicAdd(&g_pos[dd], 1);
            g_edge[p] = make_int2(ss, __float_as_int(g_dis[ss]));
        }
    }
}

// split + transpose W1: [k][n] fp32 -> [n][k] fp16 hi/lo
__global__ void k_prepB(const float* __restrict__ W1) {
    int k = blockIdx.x;        // 0..511
    int n = threadIdx.x;       // 0..255
    float v = W1[k * F1 + n];
    __half hb = __float2half_rn(v);
    __half lb = __float2half_rn(v - __half2float(hb));
    g_Bhi[(size_t)n * F0 + k] = *(uint16_t*)&hb;
    g_Blo[(size_t)n * F0 + k] = *(uint16_t*)&lb;
}

// ---------------- GEMM1 via mma.sync fp16, split-B ---------------------------
// C[M x 256] = A[M x 512] * B^T; A cast fp16, B = Bh + Bl (fp16 split).
// Grid: (2 n-tiles of 128, 782 m-tiles of 128). 256 threads, 8 warps.
// Warp grid 4(m) x 2(n): warp tile 32 x 64. k-step 32, double buffer.
// smem buffer layout (bytes): Ah[128 rows x 80B] @0, Bhi @10240, Blo @20480
#define BUFB 30720
#define G1_SMEM (2 * BUFB)

__global__ __launch_bounds__(256)
void k_mma1(const float* __restrict__ x) {
    extern __shared__ char smem[];
    const uint32_t sb = smem_u32(smem);
    const int tid = threadIdx.x;
    const int lane = tid & 31;
    const int warp = tid >> 5;
    const int warp_m = warp & 3;        // 0..3
    const int warp_n = warp >> 2;       // 0..1
    const int m0 = blockIdx.y * 128;
    const int n0 = blockIdx.x * 128;

    // ---- B loader: 1024 16B chunks per k-step, 4 per thread -----------------
    auto issue_B = [&](int it, int buf) {
        const int k0 = it * 32;
#pragma unroll
        for (int r = 0; r < 4; r++) {
            int c = tid + r * 256;
            int sel  = c >> 9;            // 0: Bhi, 1: Blo
            int row  = (c & 511) >> 2;
            int part = c & 3;
            uint32_t dstp = sb + buf * BUFB + 10240 + sel * 10240 + row * 80 + part * 16;
            const uint16_t* srcb = sel ? g_Blo : g_Bhi;
            cp_async16(dstp, srcb + (size_t)(n0 + row) * F0 + k0 + part * 8);
        }
        cp_commit();
    };

    // ---- A loader: fp32 from x, 16 floats per thread ------------------------
    const int arow_ld = tid >> 1;            // 0..127
    const int ahalf   = (tid & 1) * 16;      // k offset within step
    int grow = m0 + arow_ld;
    if (grow >= NNODES) grow = NNODES - 1;   // pad rows: duplicate (discarded)
    const float* aptr = x + (size_t)grow * F0 + ahalf;

    float areg[16];
    auto load_A = [&](int it) {
        const float4* p = (const float4*)(aptr + it * 32);
#pragma unroll
        for (int q = 0; q < 4; q++) *(float4*)(areg + q * 4) = p[q];
    };
    auto store_A = [&](int buf) {
        char* ahi = smem + buf * BUFB;
        uint32_t soff = (uint32_t)arow_ld * 80 + (uint32_t)ahalf * 2;
        uint4 h0, h1;
        cvt8(areg,     h0);
        cvt8(areg + 8, h1);
        *(uint4*)(ahi + soff)      = h0;
        *(uint4*)(ahi + soff + 16) = h1;
    };

    float acc[2][8][4];
#pragma unroll
    for (int mf = 0; mf < 2; mf++)
#pragma unroll
        for (int nf = 0; nf < 8; nf++)
#pragma unroll
            for (int j = 0; j < 4; j++) acc[mf][nf][j] = 0.f;

    issue_B(0, 0);
    issue_B(1, 1);
    load_A(0);

    const int arow  = (lane >> 2);       // 0..7
    const int acol2 = (lane & 3) * 2;    // 0,2,4,6

    // ldmatrix lane offsets
    const uint32_t aOff = (uint32_t)((warp_m * 32 + (lane & 15)) * 80 + ((lane >> 4) & 1) * 16);
    const int bmat = lane >> 3;
    const uint32_t bOff = (uint32_t)((warp_n * 64 + (bmat >> 1) * 8 + (lane & 7)) * 80 + (bmat & 1) * 16);

    for (int it = 0; it < 16; it++) {
        const int buf = it & 1;
        store_A(buf);
        if (it < 15) asm volatile("cp.async.wait_group 1;" ::: "memory");
        else         asm volatile("cp.async.wait_group 0;" ::: "memory");
        __syncthreads();
        if (it + 1 < 16) load_A(it + 1);     // LDGs in flight during MMAs

        const uint32_t sAhi = sb + buf * BUFB;
        const uint32_t sBhi = sAhi + 10240;
        const uint32_t sBlo = sAhi + 20480;

#pragma unroll
        for (int h = 0; h < 2; h++) {        // two k16 halves of the k32 tile
            const uint32_t hB = (uint32_t)h * 32;     // 16 cols * 2B
            uint32_t Ah[2][4], Bh[8][2], Bl[8][2];
#pragma unroll
            for (int mf = 0; mf < 2; mf++) {
                uint32_t off = aOff + (uint32_t)mf * (16 * 80) + hB;
                ldm_x4(Ah[mf][0], Ah[mf][1], Ah[mf][2], Ah[mf][3], sAhi + off);
            }
#pragma unroll
            for (int p = 0; p < 4; p++) {    // each x4 covers nf=2p, 2p+1
                uint32_t off = bOff + (uint32_t)p * (16 * 80) + hB;
                ldm_x4(Bh[2 * p][0], Bh[2 * p][1], Bh[2 * p + 1][0], Bh[2 * p + 1][1], sBhi + off);
                ldm_x4(Bl[2 * p][0], Bl[2 * p][1], Bl[2 * p + 1][0], Bl[2 * p + 1][1], sBlo + off);
            }
#pragma unroll
            for (int mf = 0; mf < 2; mf++)
#pragma unroll
                for (int nf = 0; nf < 8; nf++) {
                    mma_fp16(acc[mf][nf], Ah[mf], Bh[nf]);
                    mma_fp16(acc[mf][nf], Ah[mf], Bl[nf]);
                }
        }
        __syncthreads();
        if (it + 2 < 16) issue_B(it + 2, buf);
    }

    // epilogue: write accumulators to g_h1h (fp16, padded rows -> no guards)
#pragma unroll
    for (int mf = 0; mf < 2; mf++) {
        int r0 = m0 + warp_m * 32 + mf * 16 + arow;
        int r1 = r0 + 8;
#pragma unroll
        for (int nf = 0; nf < 8; nf++) {
            int col = n0 + warp_n * 64 + nf * 8 + acol2;
            __half2 p0 = __floats2half2_rn(acc[mf][nf][0], acc[mf][nf][1]);
            __half2 p1 = __floats2half2_rn(acc[mf][nf][2], acc[mf][nf][3]);
            *(uint32_t*)(g_h1h + (size_t)r0 * F1 + col) = *(uint32_t*)&p0;
            *(uint32_t*)(g_h1h + (size_t)r1 * F1 + col) = *(uint32_t*)&p1;
        }
    }
}

// ---------------- agg1: h1a = relu( Â h1 + b1 ) ------------------------------
// One 64-thread block per node; thread t owns features [4t, 4t+4) (fp16 h1).
__global__ __launch_bounds__(64)
void k_agg1(const float* __restrict__ b1) {
    const int node = blockIdx.x;
    const int t = threadIdx.x;
    const float di = g_dis[node];
    const int col = t * 4;

    float4 acc;
    {
        uint2 v = *(const uint2*)(g_h1h + (size_t)node * F1 + col);
        float2 lo = __half22float2(*(const __half2*)&v.x);
        float2 hi = __half22float2(*(const __half2*)&v.y);
        const float w0 = di * di;
        acc.x = lo.x * w0; acc.y = lo.y * w0;
        acc.z = hi.x * w0; acc.w = hi.y * w0;
    }

    const int beg = g_off[node], end = g_off[node + 1];
#pragma unroll 4
    for (int e = beg; e < end; e++) {
        int2 ed = g_edge[e];
        float w = di * __int_as_float(ed.y);
        uint2 v = *(const uint2*)(g_h1h + (size_t)ed.x * F1 + col);
        float2 lo = __half22float2(*(const __half2*)&v.x);
        float2 hi = __half22float2(*(const __half2*)&v.y);
        acc.x += lo.x * w; acc.y += lo.y * w;
        acc.z += hi.x * w; acc.w += hi.y * w;
    }
    float4 bb = *(const float4*)(b1 + col);
    acc.x = fmaxf(acc.x + bb.x, 0.f);
    acc.y = fmaxf(acc.y + bb.y, 0.f);
    acc.z = fmaxf(acc.z + bb.z, 0.f);
    acc.w = fmaxf(acc.w + bb.w, 0.f);
    __stcs((float4*)(g_h1a + (size_t)node * F1 + col), acc);   // evict-first
}

// ---------------- GEMM2: g_h2 = h1a[100000x256] @ W2[256x40] -----------------
__global__ __launch_bounds__(256)
void k_gemm2(const float* __restrict__ W2) {
    __shared__ float Ws[F1 * 41];
    const int tid = threadIdx.x;
    for (int i = tid; i < F1 * F2; i += 256) {
        int k = i / F2, j = i % F2;
        Ws[k * 41 + j] = W2[i];
    }
    __syncthreads();
    const int warp = tid >> 5, lane = tid & 31;
    const int row = blockIdx.x * 8 + warp;
    if (row >= NNODES) return;

    float acc[F2];
#pragma unroll
    for (int j = 0; j < F2; j++) acc[j] = 0.f;

    for (int k = lane; k < F1; k += 32) {
        float a = __ldcs(g_h1a + (size_t)row * F1 + k);        // read-once stream
        const float* w = &Ws[k * 41];
#pragma unroll
        for (int j = 0; j < F2; j++) acc[j] += a * w[j];
    }
#pragma unroll
    for (int j = 0; j < F2; j++) {
        float v = acc[j];
        v += __shfl_xor_sync(0xffffffffu, v, 16);
        v += __shfl_xor_sync(0xffffffffu, v, 8);
        v += __shfl_xor_sync(0xffffffffu, v, 4);
        v += __shfl_xor_sync(0xffffffffu, v, 2);
        v += __shfl_xor_sync(0xffffffffu, v, 1);
        acc[j] = v;
    }
    if (lane == 0) {
        float* out = g_h2 + (size_t)row * F2;
#pragma unroll
        for (int j = 0; j < F2; j++) out[j] = acc[j];
    }
}

// ---------------- agg2 + bias + log_softmax -> d_out -------------------------
__global__ __launch_bounds__(128)
void k_agg2(const float* __restrict__ b2, float* __restrict__ out) {
    const int node = blockIdx.x * 4 + (threadIdx.x >> 5);
    const int lane = threadIdx.x & 31;
    if (node >= NNODES) return;
    const float di = g_dis[node];

    float a0, a1 = 0.f;
    {
        const float w0 = di * di;
        const float* h = g_h2 + (size_t)node * F2;
        a0 = h[lane] * w0;
        if (lane < 8) a1 = h[32 + lane] * w0;
    }
    const int beg = g_off[node], end = g_off[node + 1];
#pragma unroll 4
    for (int e = beg; e < end; e++) {
        int2 ed = g_edge[e];
        float w = di * __int_as_float(ed.y);
        const float* h = g_h2 + (size_t)ed.x * F2;
        a0 += h[lane] * w;
        if (lane < 8) a1 += h[32 + lane] * w;
    }
    a0 += b2[lane];
    a1 = (lane < 8) ? (a1 + b2[32 + lane]) : -3.4e38f;

    float m = fmaxf(a0, a1);
    m = fmaxf(m, __shfl_xor_sync(0xffffffffu, m, 16));
    m = fmaxf(m, __shfl_xor_sync(0xffffffffu, m, 8));
    m = fmaxf(m, __shfl_xor_sync(0xffffffffu, m, 4));
    m = fmaxf(m, __shfl_xor_sync(0xffffffffu, m, 2));
    m = fmaxf(m, __shfl_xor_sync(0xffffffffu, m, 1));
    float s0 = expf(a0 - m) + ((lane < 8) ? expf(a1 - m) : 0.f);
    s0 += __shfl_xor_sync(0xffffffffu, s0, 16);
    s0 += __shfl_xor_sync(0xffffffffu, s0, 8);
    s0 += __shfl_xor_sync(0xffffffffu, s0, 4);
    s0 += __shfl_xor_sync(0xffffffffu, s0, 2);
    s0 += __shfl_xor_sync(0xffffffffu, s0, 1);
    const float ls = logf(s0) + m;

    float* o = out + (size_t)node * F2;
    __stcs(o + lane, a0 - ls);
    if (lane < 8) __stcs(o + 32 + lane, a1 - ls);
}

// ---------------- launch -----------------------------------------------------
extern "C" void kernel_launch(void* const* d_in, const int* in_sizes, int n_in,
                              void* d_out, int out_size) {
    const float* x   = (const float*)d_in[0];
    const float* W1  = (const float*)d_in[1];
    const float* b1  = (const float*)d_in[2];
    const float* W2  = (const float*)d_in[3];
    const float* b2  = (const float*)d_in[4];
    const int*   ei  = (const int*)d_in[5];
    const int*   src = ei;
    const int*   dst = ei + EDGES;
    float* out = (float*)d_out;

    static void* cnt_addr = nullptr;
    if (!cnt_addr) {
        cudaFuncSetAttribute(k_mma1, cudaFuncAttributeMaxDynamicSharedMemorySize, G1_SMEM);
        cudaGetSymbolAddress(&cnt_addr, g_cnt);
    }

    cudaMemsetAsync(cnt_addr, 0, NNODES * sizeof(int));
    k_count   <<<(EDGES / 4 + 255) / 256, 256>>>(dst);
    k_scan    <<<1, 1024>>>();
    k_fill    <<<(EDGES / 4 + 255) / 256, 256>>>(src, dst);

    k_prepB<<<F0, F1>>>(W1);

    dim3 g1(2, MPAD / 128);
    k_mma1<<<g1, 256, G1_SMEM>>>(x);

    k_agg1  <<<NNODES, 64>>>(b1);
    k_gemm2 <<<(NNODES + 7) / 8, 256>>>(W2);
    k_agg2  <<<(NNODES + 3) / 4, 128>>>(b2, out);
}

// round 9
// speedup vs baseline: 1.8231x; 1.0912x over previous
#include <cuda_runtime.h>
#include <cuda_bf16.h>
#include <cuda_fp16.h>
#include <math.h>
#include <stdint.h>

// Problem constants (fixed by setup_inputs)
#define NNODES 100000
#define F0 512
#define F1 256
#define F2 40
#define EDGES 3200000

#define MPAD 100096            // 782 * 128

// ---------------- scratch (device globals; no allocations allowed) ----------
__device__ float g_dis[NNODES];            // deg_inv_sqrt
__device__ int   g_cnt[NNODES];            // in-degree (excl. self loop)
__device__ int   g_off[NNODES + 1];        // CSR offsets by dst
__device__ int   g_pos[NNODES];            // fill cursors
__device__ int2  g_edge[EDGES];            // packed (src, dis[src] bits)
__device__ uint16_t g_h1h [(size_t)MPAD * F1];   // x @ W1            (fp16)
__device__ uint16_t g_h1ah[(size_t)NNODES * F1]; // relu(agg(h1)+b1)  (fp16)
__device__ float g_h2 [(size_t)NNODES * F2];     // h1a @ W2

// fp16-split W1 for HMMA GEMM1 (transposed [n][k])
__device__ uint16_t g_Bhi [(size_t)F1 * F0];
__device__ uint16_t g_Blo [(size_t)F1 * F0];

// ---------------- small helpers ---------------------------------------------
__device__ __forceinline__ uint32_t smem_u32(const void* p) {
    uint32_t a;
    asm("{ .reg .u64 t; cvta.to.shared.u64 t, %1; cvt.u32.u64 %0, t; }" : "=r"(a) : "l"(p));
    return a;
}
__device__ __forceinline__ void cp_async16(uint32_t dst, const void* src) {
    asm volatile("cp.async.cg.shared.global [%0], [%1], 16;" :: "r"(dst), "l"(src) : "memory");
}
__device__ __forceinline__ void cp_commit() {
    asm volatile("cp.async.commit_group;" ::: "memory");
}
__device__ __forceinline__ void mma_fp16(float* c, const uint32_t* a, const uint32_t* b) {
    asm volatile(
        "mma.sync.aligned.m16n8k16.row.col.f32.f16.f16.f32 "
        "{%0,%1,%2,%3}, {%4,%5,%6,%7}, {%8,%9}, {%0,%1,%2,%3};"
        : "+f"(c[0]), "+f"(c[1]), "+f"(c[2]), "+f"(c[3])
        : "r"(a[0]), "r"(a[1]), "r"(a[2]), "r"(a[3]), "r"(b[0]), "r"(b[1]));
}
__device__ __forceinline__ void ldm_x4(uint32_t& r0, uint32_t& r1, uint32_t& r2, uint32_t& r3,
                                       uint32_t addr) {
    asm volatile("ldmatrix.sync.aligned.m8n8.x4.shared.b16 {%0,%1,%2,%3}, [%4];"
                 : "=r"(r0), "=r"(r1), "=r"(r2), "=r"(r3) : "r"(addr));
}
// convert 8 floats to packed fp16 (uint4)
__device__ __forceinline__ void cvt8(const float* f, uint4& h) {
    uint16_t hh[8];
#pragma unroll
    for (int j = 0; j < 8; j++) {
        __half hb = __float2half_rn(f[j]);
        hh[j] = *(uint16_t*)&hb;
    }
    h = *(uint4*)hh;
}

// ---------------- CSR build --------------------------------------------------
__global__ void k_count(const int* __restrict__ dst) {
    int i = blockIdx.x * blockDim.x + threadIdx.x;      // i < EDGES/4
    int4 d = ((const int4*)dst)[i];
    if ((unsigned)d.x < (unsigned)NNODES) atomicAdd(&g_cnt[d.x], 1);
    if ((unsigned)d.y < (unsigned)NNODES) atomicAdd(&g_cnt[d.y], 1);
    if ((unsigned)d.z < (unsigned)NNODES) atomicAdd(&g_cnt[d.z], 1);
    if ((unsigned)d.w < (unsigned)NNODES) atomicAdd(&g_cnt[d.w], 1);
}

__global__ void k_scan() {
    __shared__ int part[1024];
    const int t  = threadIdx.x;
    const int CH = (NNODES + 1023) / 1024;
    int lo = t * CH;
    int hi = lo + CH; if (hi > NNODES) hi = NNODES;
    int s = 0;
    for (int i = lo; i < hi; i++) s += g_cnt[i];
    part[t] = s;
    __syncthreads();
    for (int d = 1; d < 1024; d <<= 1) {
        int add = (t >= d) ? part[t - d] : 0;
        __syncthreads();
        part[t] += add;
        __syncthreads();
    }
    int run = part[t] - s;
    for (int i = lo; i < hi; i++) {
        int c = g_cnt[i];
        g_off[i] = run;
        g_pos[i] = run;
        g_dis[i] = rsqrtf((float)(c + 1));
        run += c;
    }
    if (t == 1023) g_off[NNODES] = run;
}

__global__ void k_fill(const int* __restrict__ src,
                       const int* __restrict__ dst) {
    int i = blockIdx.x * blockDim.x + threadIdx.x;      // i < EDGES/4
    int4 d = ((const int4*)dst)[i];
    int4 s = ((const int4*)src)[i];
#pragma unroll
    for (int j = 0; j < 4; j++) {
        int dd = (&d.x)[j];
        int ss = (&s.x)[j];
        if ((unsigned)dd < (unsigned)NNODES && (unsigned)ss < (unsigned)NNODES) {
            int p = atomicAdd(&g_pos[dd], 1);
            g_edge[p] = make_int2(ss, __float_as_int(g_dis[ss]));
        }
    }
}

// split + transpose W1: [k][n] fp32 -> [n][k] fp16 hi/lo
__global__ void k_prepB(const float* __restrict__ W1) {
    int k = blockIdx.x;        // 0..511
    int n = threadIdx.x;       // 0..255
    float v = W1[k * F1 + n];
    __half hb = __float2half_rn(v);
    __half lb = __float2half_rn(v - __half2float(hb));
    g_Bhi[(size_t)n * F0 + k] = *(uint16_t*)&hb;
    g_Blo[(size_t)n * F0 + k] = *(uint16_t*)&lb;
}

// ---------------- GEMM1 via mma.sync fp16, split-B ---------------------------
// C[M x 256] = A[M x 512] * B^T; A cast fp16, B = Bh + Bl (fp16 split).
// Grid: (2 n-tiles of 128, 782 m-tiles of 128). 256 threads, 8 warps.
// Warp grid 4(m) x 2(n): warp tile 32 x 64. k-step 32, double buffer.
// smem buffer layout (bytes): Ah[128 rows x 80B] @0, Bhi @10240, Blo @20480
#define BUFB 30720
#define G1_SMEM (2 * BUFB)

__global__ __launch_bounds__(256)
void k_mma1(const float* __restrict__ x) {
    extern __shared__ char smem[];
    const uint32_t sb = smem_u32(smem);
    const int tid = threadIdx.x;
    const int lane = tid & 31;
    const int warp = tid >> 5;
    const int warp_m = warp & 3;        // 0..3
    const int warp_n = warp >> 2;       // 0..1
    const int m0 = blockIdx.y * 128;
    const int n0 = blockIdx.x * 128;

    // ---- B loader: 1024 16B chunks per k-step, 4 per thread -----------------
    auto issue_B = [&](int it, int buf) {
        const int k0 = it * 32;
#pragma unroll
        for (int r = 0; r < 4; r++) {
            int c = tid + r * 256;
            int sel  = c >> 9;            // 0: Bhi, 1: Blo
            int row  = (c & 511) >> 2;
            int part = c & 3;
            uint32_t dstp = sb + buf * BUFB + 10240 + sel * 10240 + row * 80 + part * 16;
            const uint16_t* srcb = sel ? g_Blo : g_Bhi;
            cp_async16(dstp, srcb + (size_t)(n0 + row) * F0 + k0 + part * 8);
        }
        cp_commit();
    };

    // ---- A loader: fp32 from x, 16 floats per thread ------------------------
    const int arow_ld = tid >> 1;            // 0..127
    const int ahalf   = (tid & 1) * 16;      // k offset within step
    int grow = m0 + arow_ld;
    if (grow >= NNODES) grow = NNODES - 1;   // pad rows: duplicate (discarded)
    const float* aptr = x + (size_t)grow * F0 + ahalf;

    float areg[16];
    auto load_A = [&](int it) {
        const float4* p = (const float4*)(aptr + it * 32);
#pragma unroll
        for (int q = 0; q < 4; q++) *(float4*)(areg + q * 4) = p[q];
    };
    auto store_A = [&](int buf) {
        char* ahi = smem + buf * BUFB;
        uint32_t soff = (uint32_t)arow_ld * 80 + (uint32_t)ahalf * 2;
        uint4 h0, h1;
        cvt8(areg,     h0);
        cvt8(areg + 8, h1);
        *(uint4*)(ahi + soff)      = h0;
        *(uint4*)(ahi + soff + 16) = h1;
    };

    float acc[2][8][4];
#pragma unroll
    for (int mf = 0; mf < 2; mf++)
#pragma unroll
        for (int nf = 0; nf < 8; nf++)
#pragma unroll
            for (int j = 0; j < 4; j++) acc[mf][nf][j] = 0.f;

    issue_B(0, 0);
    issue_B(1, 1);
    load_A(0);

    const int arow  = (lane >> 2);       // 0..7
    const int acol2 = (lane & 3) * 2;    // 0,2,4,6

    // ldmatrix lane offsets
    const uint32_t aOff = (uint32_t)((warp_m * 32 + (lane & 15)) * 80 + ((lane >> 4) & 1) * 16);
    const int bmat = lane >> 3;
    const uint32_t bOff = (uint32_t)((warp_n * 64 + (bmat >> 1) * 8 + (lane & 7)) * 80 + (bmat & 1) * 16);

    for (int it = 0; it < 16; it++) {
        const int buf = it & 1;
        store_A(buf);
        if (it < 15) asm volatile("cp.async.wait_group 1;" ::: "memory");
        else         asm volatile("cp.async.wait_group 0;" ::: "memory");
        __syncthreads();
        if (it + 1 < 16) load_A(it + 1);     // LDGs in flight during MMAs

        const uint32_t sAhi = sb + buf * BUFB;
        const uint32_t sBhi = sAhi + 10240;
        const uint32_t sBlo = sAhi + 20480;

#pragma unroll
        for (int h = 0; h < 2; h++) {        // two k16 halves of the k32 tile
            const uint32_t hB = (uint32_t)h * 32;     // 16 cols * 2B
            uint32_t Ah[2][4], Bh[8][2], Bl[8][2];
#pragma unroll
            for (int mf = 0; mf < 2; mf++) {
                uint32_t off = aOff + (uint32_t)mf * (16 * 80) + hB;
                ldm_x4(Ah[mf][0], Ah[mf][1], Ah[mf][2], Ah[mf][3], sAhi + off);
            }
#pragma unroll
            for (int p = 0; p < 4; p++) {    // each x4 covers nf=2p, 2p+1
                uint32_t off = bOff + (uint32_t)p * (16 * 80) + hB;
                ldm_x4(Bh[2 * p][0], Bh[2 * p][1], Bh[2 * p + 1][0], Bh[2 * p + 1][1], sBhi + off);
                ldm_x4(Bl[2 * p][0], Bl[2 * p][1], Bl[2 * p + 1][0], Bl[2 * p + 1][1], sBlo + off);
            }
#pragma unroll
            for (int mf = 0; mf < 2; mf++)
#pragma unroll
                for (int nf = 0; nf < 8; nf++) {
                    mma_fp16(acc[mf][nf], Ah[mf], Bh[nf]);
                    mma_fp16(acc[mf][nf], Ah[mf], Bl[nf]);
                }
        }
        __syncthreads();
        if (it + 2 < 16) issue_B(it + 2, buf);
    }

    // epilogue: write accumulators to g_h1h (fp16, padded rows -> no guards)
#pragma unroll
    for (int mf = 0; mf < 2; mf++) {
        int r0 = m0 + warp_m * 32 + mf * 16 + arow;
        int r1 = r0 + 8;
#pragma unroll
        for (int nf = 0; nf < 8; nf++) {
            int col = n0 + warp_n * 64 + nf * 8 + acol2;
            __half2 p0 = __floats2half2_rn(acc[mf][nf][0], acc[mf][nf][1]);
            __half2 p1 = __floats2half2_rn(acc[mf][nf][2], acc[mf][nf][3]);
            *(uint32_t*)(g_h1h + (size_t)r0 * F1 + col) = *(uint32_t*)&p0;
            *(uint32_t*)(g_h1h + (size_t)r1 * F1 + col) = *(uint32_t*)&p1;
        }
    }
}

// ---------------- agg1: h1a = relu( Â h1 + b1 ) ------------------------------
// One 64-thread block per node; thread t owns features [4t, 4t+4) (fp16).
__global__ __launch_bounds__(64)
void k_agg1(const float* __restrict__ b1) {
    const int node = blockIdx.x;
    const int t = threadIdx.x;
    const float di = g_dis[node];
    const int col = t * 4;

    float4 acc;
    {
        uint2 v = *(const uint2*)(g_h1h + (size_t)node * F1 + col);
        float2 lo = __half22float2(*(const __half2*)&v.x);
        float2 hi = __half22float2(*(const __half2*)&v.y);
        const float w0 = di * di;
        acc.x = lo.x * w0; acc.y = lo.y * w0;
        acc.z = hi.x * w0; acc.w = hi.y * w0;
    }

    const int beg = g_off[node], end = g_off[node + 1];
#pragma unroll 4
    for (int e = beg; e < end; e++) {
        int2 ed = g_edge[e];
        float w = di * __int_as_float(ed.y);
        uint2 v = *(const uint2*)(g_h1h + (size_t)ed.x * F1 + col);
        float2 lo = __half22float2(*(const __half2*)&v.x);
        float2 hi = __half22float2(*(const __half2*)&v.y);
        acc.x += lo.x * w; acc.y += lo.y * w;
        acc.z += hi.x * w; acc.w += hi.y * w;
    }
    float4 bb = *(const float4*)(b1 + col);
    acc.x = fmaxf(acc.x + bb.x, 0.f);
    acc.y = fmaxf(acc.y + bb.y, 0.f);
    acc.z = fmaxf(acc.z + bb.z, 0.f);
    acc.w = fmaxf(acc.w + bb.w, 0.f);
    __half2 p0 = __floats2half2_rn(acc.x, acc.y);
    __half2 p1 = __floats2half2_rn(acc.z, acc.w);
    uint2 pk = make_uint2(*(uint32_t*)&p0, *(uint32_t*)&p1);
    __stcs((uint2*)(g_h1ah + (size_t)node * F1 + col), pk);    // evict-first
}

// ---------------- GEMM2: g_h2 = h1a[100000x256] @ W2[256x40] (fp16 in) -------
__global__ __launch_bounds__(256)
void k_gemm2(const float* __restrict__ W2) {
    __shared__ float Ws[F1 * 41];
    const int tid = threadIdx.x;
    for (int i = tid; i < F1 * F2; i += 256) {
        int k = i / F2, j = i % F2;
        Ws[k * 41 + j] = W2[i];
    }
    __syncthreads();
    const int warp = tid >> 5, lane = tid & 31;
    const int row = blockIdx.x * 8 + warp;
    if (row >= NNODES) return;

    float acc[F2];
#pragma unroll
    for (int j = 0; j < F2; j++) acc[j] = 0.f;

    for (int kk = lane; kk < F1 / 2; kk += 32) {     // kk indexes half2 pairs
        uint32_t v = __ldcs((const uint32_t*)g_h1ah + (size_t)row * (F1 / 2) + kk);
        float2 a = __half22float2(*(const __half2*)&v);
        const float* w0 = &Ws[(2 * kk) * 41];
        const float* w1 = &Ws[(2 * kk + 1) * 41];
#pragma unroll
        for (int j = 0; j < F2; j++) acc[j] += a.x * w0[j] + a.y * w1[j];
    }
#pragma unroll
    for (int j = 0; j < F2; j++) {
        float v = acc[j];
        v += __shfl_xor_sync(0xffffffffu, v, 16);
        v += __shfl_xor_sync(0xffffffffu, v, 8);
        v += __shfl_xor_sync(0xffffffffu, v, 4);
        v += __shfl_xor_sync(0xffffffffu, v, 2);
        v += __shfl_xor_sync(0xffffffffu, v, 1);
        acc[j] = v;
    }
    if (lane == 0) {
        float* out = g_h2 + (size_t)row * F2;
#pragma unroll
        for (int j = 0; j < F2; j++) out[j] = acc[j];
    }
}

// ---------------- agg2 + bias + log_softmax -> d_out -------------------------
__global__ __launch_bounds__(128)
void k_agg2(const float* __restrict__ b2, float* __restrict__ out) {
    const int node = blockIdx.x * 4 + (threadIdx.x >> 5);
    const int lane = threadIdx.x & 31;
    if (node >= NNODES) return;
    const float di = g_dis[node];

    float a0, a1 = 0.f;
    {
        const float w0 = di * di;
        const float* h = g_h2 + (size_t)node * F2;
        a0 = h[lane] * w0;
        if (lane < 8) a1 = h[32 + lane] * w0;
    }
    const int beg = g_off[node], end = g_off[node + 1];
#pragma unroll 4
    for (int e = beg; e < end; e++) {
        int2 ed = g_edge[e];
        float w = di * __int_as_float(ed.y);
        const float* h = g_h2 + (size_t)ed.x * F2;
        a0 += h[lane] * w;
        if (lane < 8) a1 += h[32 + lane] * w;
    }
    a0 += b2[lane];
    a1 = (lane < 8) ? (a1 + b2[32 + lane]) : -3.4e38f;

    float m = fmaxf(a0, a1);
    m = fmaxf(m, __shfl_xor_sync(0xffffffffu, m, 16));
    m = fmaxf(m, __shfl_xor_sync(0xffffffffu, m, 8));
    m = fmaxf(m, __shfl_xor_sync(0xffffffffu, m, 4));
    m = fmaxf(m, __shfl_xor_sync(0xffffffffu, m, 2));
    m = fmaxf(m, __shfl_xor_sync(0xffffffffu, m, 1));
    float s0 = expf(a0 - m) + ((lane < 8) ? expf(a1 - m) : 0.f);
    s0 += __shfl_xor_sync(0xffffffffu, s0, 16);
    s0 += __shfl_xor_sync(0xffffffffu, s0, 8);
    s0 += __shfl_xor_sync(0xffffffffu, s0, 4);
    s0 += __shfl_xor_sync(0xffffffffu, s0, 2);
    s0 += __shfl_xor_sync(0xffffffffu, s0, 1);
    const float ls = logf(s0) + m;

    float* o = out + (size_t)node * F2;
    __stcs(o + lane, a0 - ls);
    if (lane < 8) __stcs(o + 32 + lane, a1 - ls);
}

// ---------------- launch -----------------------------------------------------
extern "C" void kernel_launch(void* const* d_in, const int* in_sizes, int n_in,
                              void* d_out, int out_size) {
    const float* x   = (const float*)d_in[0];
    const float* W1  = (const float*)d_in[1];
    const float* b1  = (const float*)d_in[2];
    const float* W2  = (const float*)d_in[3];
    const float* b2  = (const float*)d_in[4];
    const int*   ei  = (const int*)d_in[5];
    const int*   src = ei;
    const int*   dst = ei + EDGES;
    float* out = (float*)d_out;

    static void* cnt_addr = nullptr;
    static cudaStream_t s2 = nullptr;
    static cudaEvent_t evFork = nullptr, evJoin = nullptr;
    if (!cnt_addr) {
        cudaFuncSetAttribute(k_mma1, cudaFuncAttributeMaxDynamicSharedMemorySize, G1_SMEM);
        cudaGetSymbolAddress(&cnt_addr, g_cnt);
        cudaStreamCreateWithFlags(&s2, cudaStreamNonBlocking);
        cudaEventCreateWithFlags(&evFork, cudaEventDisableTiming);
        cudaEventCreateWithFlags(&evJoin, cudaEventDisableTiming);
    }

    // ---- fork: CSR build on side stream, GEMM1 path on main stream ----------
    cudaEventRecord(evFork, 0);
    cudaStreamWaitEvent(s2, evFork, 0);

    cudaMemsetAsync(cnt_addr, 0, NNODES * sizeof(int), s2);
    k_count<<<(EDGES / 4 + 255) / 256, 256, 0, s2>>>(dst);
    k_scan <<<1, 1024, 0, s2>>>();
    k_fill <<<(EDGES / 4 + 255) / 256, 256, 0, s2>>>(src, dst);
    cudaEventRecord(evJoin, s2);

    k_prepB<<<F0, F1>>>(W1);
    dim3 g1(2, MPAD / 128);
    k_mma1<<<g1, 256, G1_SMEM>>>(x);

    // ---- join ----------------------------------------------------------------
    cudaStreamWaitEvent(0, evJoin, 0);

    k_agg1  <<<NNODES, 64>>>(b1);
    k_gemm2 <<<(NNODES + 7) / 8, 256>>>(W2);
    k_agg2  <<<(NNODES + 3) / 4, 128>>>(b2, out);
}